// round 12
// baseline (speedup 1.0000x reference)
#include <cuda_runtime.h>
#include <cuda_bf16.h>
#include <cuda_fp16.h>
#include <cstdint>
#include <math.h>

#define BATCH 2
#define SEQ   2048
#define EMB   2048
#define NHEAD 16
#define DHEAD 128
#define NEXP_ 64
#define RLORA 32
#define ROWS  4096
#define KAUG  2144

// ---------------- scratch ----------------
__device__ float g_q[(size_t)ROWS * EMB];
__device__ float g_k[(size_t)ROWS * EMB];
__device__ float g_v[(size_t)ROWS * EMB];
__device__ float g_att[(size_t)ROWS * EMB];
__device__ float g_haux[4][(size_t)ROWS * 96];
__device__ unsigned g_kph[(size_t)32 * 2048 * 64];
__device__ unsigned g_kpl[(size_t)32 * 2048 * 64];
__device__ unsigned g_vph[(size_t)32 * 1024 * 128];
__device__ unsigned g_vpl[(size_t)32 * 1024 * 128];

// ---------------- helpers ----------------
__device__ __forceinline__ unsigned pack_bf2(__nv_bfloat16 a, __nv_bfloat16 b) {
    return (unsigned)__bfloat16_as_ushort(a) | ((unsigned)__bfloat16_as_ushort(b) << 16);
}
__device__ __forceinline__ void split_bf(float x, __nv_bfloat16& hi, __nv_bfloat16& lo) {
    hi = __float2bfloat16_rn(x);
    lo = __float2bfloat16_rn(x - __bfloat162float(hi));
}
__device__ __forceinline__ unsigned pack_h2(__half a, __half b) {
    __half2 t = __halves2half2(a, b);
    return *(unsigned*)&t;
}
__device__ __forceinline__ void split_h_plain(float x, __half& hi, __half& lo) {
    hi = __float2half_rn(x);
    lo = __float2half_rn(x - __half2float(hi));
}
__device__ __forceinline__ void mma_bf16(float* c, const unsigned* a, const unsigned* b) {
    asm volatile(
        "mma.sync.aligned.m16n8k16.row.col.f32.bf16.bf16.f32 "
        "{%0,%1,%2,%3}, {%4,%5,%6,%7}, {%8,%9}, {%0,%1,%2,%3};"
        : "+f"(c[0]), "+f"(c[1]), "+f"(c[2]), "+f"(c[3])
        : "r"(a[0]), "r"(a[1]), "r"(a[2]), "r"(a[3]), "r"(b[0]), "r"(b[1]));
}
__device__ __forceinline__ void mma_f16_f32(float* c, const unsigned* a, const unsigned* b) {
    asm volatile(
        "mma.sync.aligned.m16n8k16.row.col.f32.f16.f16.f32 "
        "{%0,%1,%2,%3}, {%4,%5,%6,%7}, {%8,%9}, {%0,%1,%2,%3};"
        : "+f"(c[0]), "+f"(c[1]), "+f"(c[2]), "+f"(c[3])
        : "r"(a[0]), "r"(a[1]), "r"(a[2]), "r"(a[3]), "r"(b[0]), "r"(b[1]));
}

#define L2E 1.4426950408889634f

__device__ __forceinline__ float exp2q(float t) {
    t = fmaxf(t, -126.f);
    float z = t + 12582912.f;               // 1.5*2^23
    int ni = __float_as_int(z) - 0x4B400000;
    float r = t - (z - 12582912.f);
    float p = 1.3333558146e-3f;
    p = fmaf(p, r, 9.6181291876e-3f);
    p = fmaf(p, r, 5.5504108665e-2f);
    p = fmaf(p, r, 2.4022650696e-1f);
    p = fmaf(p, r, 6.9314718056e-1f);
    p = fmaf(p, r, 1.0f);
    return p * __int_as_float((ni + 127) << 23);
}

// ---------------------------------------------------------------------------
// aux GEMM on tensor cores (bf16 split), term-major MMA ordering.
// ---------------------------------------------------------------------------
__global__ __launch_bounds__(256) void aux_mma(
    const float* __restrict__ act, const float* __restrict__ mask,
    const float* __restrict__ A0, const float* __restrict__ C0,
    const float* __restrict__ A1, const float* __restrict__ C1,
    const float* __restrict__ A2, const float* __restrict__ C2,
    float* __restrict__ h0, float* __restrict__ h1, float* __restrict__ h2)
{
    __shared__ unsigned Ah[128][20], Al[128][20];
    __shared__ unsigned Bh[96][20],  Blo[96][20];

    const int proj = blockIdx.x;
    const int m0 = blockIdx.y * 128;
    const float* A = (proj == 0) ? A0 : ((proj == 1) ? A1 : A2);
    const float* C = (proj == 0) ? C0 : ((proj == 1) ? C1 : C2);
    float* hout    = (proj == 0) ? h0 : ((proj == 1) ? h1 : h2);

    const int tid = threadIdx.x;
    const int lane = tid & 31, wid = tid >> 5;
    const int l4 = lane >> 2, lk = lane & 3;
    const int warp_m = wid & 3, warp_n = wid >> 2;

    float c[2][6][4];
    #pragma unroll
    for (int mt = 0; mt < 2; mt++)
        #pragma unroll
        for (int nt = 0; nt < 6; nt++)
            #pragma unroll
            for (int i = 0; i < 4; i++) c[mt][nt][i] = 0.f;

    for (int k0 = 0; k0 < EMB; k0 += 32) {
        #pragma unroll
        for (int i = 0; i < 4; i++) {
            int lin = tid + 256 * i;
            int r = lin >> 3, c4 = (lin & 7) << 2;
            float4 va = *(const float4*)(act + (size_t)(m0 + r) * EMB + k0 + c4);
            __nv_bfloat16 hx, lx, hy, ly, hz, lz, hw, lw;
            split_bf(va.x, hx, lx); split_bf(va.y, hy, ly);
            split_bf(va.z, hz, lz); split_bf(va.w, hw, lw);
            int wofs = c4 >> 1;
            *(uint2*)&Ah[r][wofs] = make_uint2(pack_bf2(hx, hy), pack_bf2(hz, hw));
            *(uint2*)&Al[r][wofs] = make_uint2(pack_bf2(lx, ly), pack_bf2(lz, lw));
        }
        #pragma unroll
        for (int i = 0; i < 3; i++) {
            int lin = tid + 256 * i;
            if (lin < 768) {
                int r = lin >> 3, c4 = (lin & 7) << 2;
                const float* src = (r < 32) ? (A + (size_t)r * EMB)
                                            : (C + (size_t)(r - 32) * EMB);
                float4 vb = *(const float4*)(src + k0 + c4);
                __nv_bfloat16 hx, lx, hy, ly, hz, lz, hw, lw;
                split_bf(vb.x, hx, lx); split_bf(vb.y, hy, ly);
                split_bf(vb.z, hz, lz); split_bf(vb.w, hw, lw);
                int wofs = c4 >> 1;
                *(uint2*)&Bh[r][wofs]  = make_uint2(pack_bf2(hx, hy), pack_bf2(hz, hw));
                *(uint2*)&Blo[r][wofs] = make_uint2(pack_bf2(lx, ly), pack_bf2(lz, lw));
            }
        }
        __syncthreads();

        #pragma unroll
        for (int ks = 0; ks < 2; ks++) {
            const int kw = ks * 8;
            unsigned ah[2][4], al[2][4];
            #pragma unroll
            for (int mt = 0; mt < 2; mt++) {
                int rb = warp_m * 32 + mt * 16 + l4;
                ah[mt][0] = Ah[rb][kw + lk];
                ah[mt][1] = Ah[rb + 8][kw + lk];
                ah[mt][2] = Ah[rb][kw + 4 + lk];
                ah[mt][3] = Ah[rb + 8][kw + 4 + lk];
                al[mt][0] = Al[rb][kw + lk];
                al[mt][1] = Al[rb + 8][kw + lk];
                al[mt][2] = Al[rb][kw + 4 + lk];
                al[mt][3] = Al[rb + 8][kw + 4 + lk];
            }
            #pragma unroll
            for (int nc = 0; nc < 2; nc++) {
                unsigned bh[3][2], bl[3][2];
                #pragma unroll
                for (int j = 0; j < 3; j++) {
                    int cb = warp_n * 48 + (nc * 3 + j) * 8 + l4;
                    bh[j][0] = Bh[cb][kw + lk];
                    bh[j][1] = Bh[cb][kw + 4 + lk];
                    bl[j][0] = Blo[cb][kw + lk];
                    bl[j][1] = Blo[cb][kw + 4 + lk];
                }
                #pragma unroll
                for (int j = 0; j < 3; j++)
                    #pragma unroll
                    for (int mt = 0; mt < 2; mt++)
                        mma_bf16(c[mt][nc * 3 + j], ah[mt], bh[j]);
                #pragma unroll
                for (int j = 0; j < 3; j++)
                    #pragma unroll
                    for (int mt = 0; mt < 2; mt++)
                        mma_bf16(c[mt][nc * 3 + j], ah[mt], bl[j]);
                #pragma unroll
                for (int j = 0; j < 3; j++)
                    #pragma unroll
                    for (int mt = 0; mt < 2; mt++)
                        mma_bf16(c[mt][nc * 3 + j], al[mt], bh[j]);
            }
        }
        __syncthreads();
    }

    #pragma unroll
    for (int mt = 0; mt < 2; mt++) {
        int r0 = m0 + warp_m * 32 + mt * 16 + l4;
        #pragma unroll
        for (int nt = 0; nt < 6; nt++) {
            int u = warp_n * 48 + nt * 8 + 2 * lk;
            #pragma unroll
            for (int half = 0; half < 2; half++) {
                int row = r0 + half * 8;
                float v0 = c[mt][nt][half * 2 + 0];
                float v1 = c[mt][nt][half * 2 + 1];
                float s0 = v0 / (1.f + __expf(-v0));
                float s1 = v1 / (1.f + __expf(-v1));
                if (u >= 32)     s0 *= mask[(size_t)row * NEXP_ + (u - 32)];
                if (u + 1 >= 32) s1 *= mask[(size_t)row * NEXP_ + (u + 1 - 32)];
                hout[(size_t)row * 96 + u]     = s0;
                hout[(size_t)row * 96 + u + 1] = s1;
            }
        }
    }
}

// ---------------------------------------------------------------------------
// K-augmented GEMM (split-bf16), term-major MMA ordering (dep-chain break).
// ---------------------------------------------------------------------------
#define GP 20

__global__ __launch_bounds__(256, 2) void gemm_mma(
    const float* __restrict__ act, const float* __restrict__ haux,
    const float* __restrict__ Wd,  const float* __restrict__ Bl,
    const float* __restrict__ Rr,  const float* __restrict__ bias,
    float* __restrict__ out)
{
    __shared__ unsigned As_hi[128][GP], As_lo[128][GP];
    __shared__ unsigned Bs_hi[128][GP], Bs_lo[128][GP];

    const int tid = threadIdx.x;
    const int lane = tid & 31, wid = tid >> 5;
    const int l4 = lane >> 2, lk = lane & 3;
    const int warp_m = wid & 3, warp_n = wid >> 2;
    const int m0 = blockIdx.y * 128, n0 = blockIdx.x * 128;

    float c[2][8][4];
    #pragma unroll
    for (int mt = 0; mt < 2; mt++)
        #pragma unroll
        for (int nt = 0; nt < 8; nt++)
            #pragma unroll
            for (int i = 0; i < 4; i++) c[mt][nt][i] = 0.f;

    for (int k0 = 0; k0 < KAUG; k0 += 32) {
        const float* asrc; int lda, kof;
        if (k0 < EMB) { asrc = act;  lda = EMB; kof = k0; }
        else          { asrc = haux; lda = 96;  kof = k0 - EMB; }

        const float* wsrc; int ldw, kofw;
        if (k0 < EMB)              { wsrc = Wd; ldw = EMB;   kofw = k0; }
        else if (k0 < EMB + RLORA) { wsrc = Bl; ldw = RLORA; kofw = k0 - EMB; }
        else                       { wsrc = Rr; ldw = NEXP_; kofw = k0 - EMB - RLORA; }

        #pragma unroll
        for (int i = 0; i < 4; i++) {
            int lin = tid + 256 * i;
            int r = lin >> 3, c4 = (lin & 7) << 2;
            float4 va = *(const float4*)(asrc + (size_t)(m0 + r) * lda + kof + c4);
            __nv_bfloat16 hx, lx, hy, ly, hz, lz, hw, lw;
            split_bf(va.x, hx, lx); split_bf(va.y, hy, ly);
            split_bf(va.z, hz, lz); split_bf(va.w, hw, lw);
            int wofs = c4 >> 1;
            *(uint2*)&As_hi[r][wofs] = make_uint2(pack_bf2(hx, hy), pack_bf2(hz, hw));
            *(uint2*)&As_lo[r][wofs] = make_uint2(pack_bf2(lx, ly), pack_bf2(lz, lw));
        }
        #pragma unroll
        for (int i = 0; i < 4; i++) {
            int lin = tid + 256 * i;
            int r = lin >> 3, c4 = (lin & 7) << 2;
            float4 vb = *(const float4*)(wsrc + (size_t)(n0 + r) * ldw + kofw + c4);
            __nv_bfloat16 hx, lx, hy, ly, hz, lz, hw, lw;
            split_bf(vb.x, hx, lx); split_bf(vb.y, hy, ly);
            split_bf(vb.z, hz, lz); split_bf(vb.w, hw, lw);
            int wofs = c4 >> 1;
            *(uint2*)&Bs_hi[r][wofs] = make_uint2(pack_bf2(hx, hy), pack_bf2(hz, hw));
            *(uint2*)&Bs_lo[r][wofs] = make_uint2(pack_bf2(lx, ly), pack_bf2(lz, lw));
        }
        __syncthreads();

        #pragma unroll
        for (int ks = 0; ks < 2; ks++) {
            const int kw = ks * 8;
            unsigned a_hi[2][4], a_lo[2][4];
            #pragma unroll
            for (int mt = 0; mt < 2; mt++) {
                int rb = warp_m * 32 + mt * 16 + l4;
                a_hi[mt][0] = As_hi[rb][kw + lk];
                a_hi[mt][1] = As_hi[rb + 8][kw + lk];
                a_hi[mt][2] = As_hi[rb][kw + 4 + lk];
                a_hi[mt][3] = As_hi[rb + 8][kw + 4 + lk];
                a_lo[mt][0] = As_lo[rb][kw + lk];
                a_lo[mt][1] = As_lo[rb + 8][kw + lk];
                a_lo[mt][2] = As_lo[rb][kw + 4 + lk];
                a_lo[mt][3] = As_lo[rb + 8][kw + 4 + lk];
            }
            #pragma unroll
            for (int nc = 0; nc < 4; nc++) {
                unsigned bh[2][2], bl[2][2];
                #pragma unroll
                for (int j = 0; j < 2; j++) {
                    int cb = warp_n * 64 + (nc * 2 + j) * 8 + l4;
                    bh[j][0] = Bs_hi[cb][kw + lk];
                    bh[j][1] = Bs_hi[cb][kw + 4 + lk];
                    bl[j][0] = Bs_lo[cb][kw + lk];
                    bl[j][1] = Bs_lo[cb][kw + 4 + lk];
                }
                #pragma unroll
                for (int j = 0; j < 2; j++)
                    #pragma unroll
                    for (int mt = 0; mt < 2; mt++)
                        mma_bf16(c[mt][nc * 2 + j], a_hi[mt], bh[j]);
                #pragma unroll
                for (int j = 0; j < 2; j++)
                    #pragma unroll
                    for (int mt = 0; mt < 2; mt++)
                        mma_bf16(c[mt][nc * 2 + j], a_hi[mt], bl[j]);
                #pragma unroll
                for (int j = 0; j < 2; j++)
                    #pragma unroll
                    for (int mt = 0; mt < 2; mt++)
                        mma_bf16(c[mt][nc * 2 + j], a_lo[mt], bh[j]);
            }
        }
        __syncthreads();
    }

    float2 bv[8];
    #pragma unroll
    for (int nt = 0; nt < 8; nt++) {
        int col = n0 + warp_n * 64 + nt * 8 + 2 * lk;
        if (bias) bv[nt] = *(const float2*)(bias + col);
        else      bv[nt] = make_float2(0.f, 0.f);
    }
    #pragma unroll
    for (int mt = 0; mt < 2; mt++) {
        int r0 = m0 + warp_m * 32 + mt * 16 + l4;
        #pragma unroll
        for (int nt = 0; nt < 8; nt++) {
            int col = n0 + warp_n * 64 + nt * 8 + 2 * lk;
            float2 o0 = make_float2(c[mt][nt][0] + bv[nt].x, c[mt][nt][1] + bv[nt].y);
            float2 o1 = make_float2(c[mt][nt][2] + bv[nt].x, c[mt][nt][3] + bv[nt].y);
            *(float2*)(out + (size_t)r0 * EMB + col)       = o0;
            *(float2*)(out + (size_t)(r0 + 8) * EMB + col) = o1;
        }
    }
}

// ---------------------------------------------------------------------------
// rope_pack: rope q in-place (fp32); rope k -> packed bf16 hi/lo
// ---------------------------------------------------------------------------
__global__ void rope_pack(float* __restrict__ q, const float* __restrict__ k,
                          unsigned* __restrict__ kph, unsigned* __restrict__ kpl)
{
    int idx = blockIdx.x * blockDim.x + threadIdx.x;
    if (idx >= ROWS * NHEAD * 32) return;
    int jj  = idx & 31;
    int h   = (idx >> 5) & 15;
    int row = idx >> 9;
    int s   = row & (SEQ - 1);
    int b   = row >> 11;

    float sn[2], cs[2];
    #pragma unroll
    for (int t = 0; t < 2; t++) {
        int d = 2 * jj + t;
        float e = (float)(2 * d) * (1.0f / 128.0f);
        float inv = powf(10000.0f, -e);
        sincosf((float)s * inv, &sn[t], &cs[t]);
    }

    size_t base = (size_t)row * EMB + h * DHEAD;
    float qlo[2], qhi2[2], klo[2], khi2[2];
    #pragma unroll
    for (int t = 0; t < 2; t++) {
        int d = 2 * jj + t;
        float x1 = q[base + d], x2 = q[base + d + 64];
        qlo[t]  = x1 * cs[t] - x2 * sn[t];
        qhi2[t] = x2 * cs[t] + x1 * sn[t];
        float y1 = k[base + d], y2 = k[base + d + 64];
        klo[t]  = y1 * cs[t] - y2 * sn[t];
        khi2[t] = y2 * cs[t] + y1 * sn[t];
    }
    #pragma unroll
    for (int t = 0; t < 2; t++) {
        q[base + 2 * jj + t]      = qlo[t];
        q[base + 2 * jj + t + 64] = qhi2[t];
    }
    int bh = b * NHEAD + h;
    size_t kbase = ((size_t)bh * SEQ + s) * 64;
    __nv_bfloat16 h0, l0, h1, l1;
    split_bf(klo[0], h0, l0); split_bf(klo[1], h1, l1);
    kph[kbase + jj] = pack_bf2(h0, h1);
    kpl[kbase + jj] = pack_bf2(l0, l1);
    split_bf(khi2[0], h0, l0); split_bf(khi2[1], h1, l1);
    kph[kbase + jj + 32] = pack_bf2(h0, h1);
    kpl[kbase + jj + 32] = pack_bf2(l0, l1);
}

// ---------------------------------------------------------------------------
// vpack: V fp16 hi/lo packed along k-pairs
// ---------------------------------------------------------------------------
__global__ void vpack(const float* __restrict__ v,
                      unsigned* __restrict__ vph, unsigned* __restrict__ vpl)
{
    int idx = blockIdx.x * blockDim.x + threadIdx.x;
    if (idx >= 32 * 1024 * 128) return;
    int nn = idx & 127;
    int kw = (idx >> 7) & 1023;
    int bh = idx >> 17;
    int b = bh >> 4, h = bh & 15;
    size_t addr = ((size_t)(b * SEQ + 2 * kw)) * EMB + h * DHEAD + nn;
    float v0 = v[addr], v1 = v[addr + EMB];
    __half h0, l0, h1, l1;
    split_h_plain(v0, h0, l0); split_h_plain(v1, h1, l1);
    vph[idx] = pack_h2(h0, h1);
    vpl[idx] = pack_h2(l0, l1);
}

// ---------------------------------------------------------------------------
// Flash attention, term-major MMA ordering in QK and PV.
// ---------------------------------------------------------------------------
#define KPP 68
#define VPP 136
#define FA2_SMEM ((64 * KPP * 2 + 32 * VPP * 2) * 4)

__global__ __launch_bounds__(256) void flash_mma(
    const float* __restrict__ q,
    const unsigned* __restrict__ kph, const unsigned* __restrict__ kpl,
    const unsigned* __restrict__ vph, const unsigned* __restrict__ vpl,
    float* __restrict__ o)
{
    extern __shared__ unsigned sw_[];
    unsigned* Kph = sw_;
    unsigned* Kpl = Kph + 64 * KPP;
    unsigned* Vph = Kpl + 64 * KPP;
    unsigned* Vpl = Vph + 32 * VPP;

    const int tid = threadIdx.x;
    const int lane = tid & 31, wm = tid >> 5;
    const int l4 = lane >> 2, lk = lane & 3;
    const int iblk = (int)gridDim.x - 1 - (int)blockIdx.x;
    const int bh = blockIdx.y;
    const int b = bh >> 4, h = bh & 15;
    const size_t rowbase = (size_t)b * SEQ;
    const int m0 = iblk * 128;
    const float scale = 0.08838834764831845f;

    unsigned qh[8][4], ql[8][4];
    {
        const int r0 = m0 + wm * 16 + l4;
        #pragma unroll
        for (int s = 0; s < 8; s++) {
            #pragma unroll
            for (int f = 0; f < 4; f++) {
                int r = r0 + ((f & 1) ? 8 : 0);
                int d = 16 * s + 2 * lk + ((f & 2) ? 8 : 0);
                float2 qv = *(const float2*)(q + (rowbase + r) * EMB + h * DHEAD + d);
                float x = qv.x * scale, y = qv.y * scale;
                __nv_bfloat16 hx, lx, hy, ly;
                split_bf(x, hx, lx); split_bf(y, hy, ly);
                qh[s][f] = pack_bf2(hx, hy);
                ql[s][f] = pack_bf2(lx, ly);
            }
        }
    }

    float mr0 = -1e30f, mr1 = -1e30f, lr0 = 0.f, lr1 = 0.f;
    float oacc[16][4];
    #pragma unroll
    for (int nt = 0; nt < 16; nt++)
        #pragma unroll
        for (int i = 0; i < 4; i++) oacc[nt][i] = 0.f;

    const size_t kbase = (size_t)bh * SEQ * 64;
    const size_t vbase = (size_t)bh * 1024 * 128;

    const int ntiles = 2 * iblk + 2;
    for (int j = 0; j < ntiles; j++) {
        #pragma unroll
        for (int i = 0; i < 4; i++) {
            int lin = tid + 256 * i;
            int r = lin >> 4, c4 = (lin & 15) << 2;
            size_t src = kbase + (size_t)(j * 64 + r) * 64 + c4;
            *(uint4*)&Kph[r * KPP + c4] = *(const uint4*)(kph + src);
            *(uint4*)&Kpl[r * KPP + c4] = *(const uint4*)(kpl + src);
        }
        #pragma unroll
        for (int i = 0; i < 4; i++) {
            int lin = tid + 256 * i;
            int r = lin >> 5, c4 = (lin & 31) << 2;
            size_t src = vbase + (size_t)(j * 32 + r) * 128 + c4;
            *(uint4*)&Vph[r * VPP + c4] = *(const uint4*)(vph + src);
            *(uint4*)&Vpl[r * VPP + c4] = *(const uint4*)(vpl + src);
        }
        __syncthreads();

        float sacc[8][4];
        #pragma unroll
        for (int nt = 0; nt < 8; nt++)
            #pragma unroll
            for (int i = 0; i < 4; i++) sacc[nt][i] = 0.f;

        #pragma unroll
        for (int s = 0; s < 8; s++) {
            #pragma unroll
            for (int nc = 0; nc < 2; nc++) {
                unsigned bh4[4][2], bl4[4][2];
                #pragma unroll
                for (int jn = 0; jn < 4; jn++) {
                    int kr = ((nc * 4 + jn) * 8 + l4) * KPP + 8 * s + lk;
                    bh4[jn][0] = Kph[kr];
                    bh4[jn][1] = Kph[kr + 4];
                    bl4[jn][0] = Kpl[kr];
                    bl4[jn][1] = Kpl[kr + 4];
                }
                #pragma unroll
                for (int jn = 0; jn < 4; jn++)
                    mma_bf16(sacc[nc * 4 + jn], qh[s], bh4[jn]);
                #pragma unroll
                for (int jn = 0; jn < 4; jn++)
                    mma_bf16(sacc[nc * 4 + jn], qh[s], bl4[jn]);
                #pragma unroll
                for (int jn = 0; jn < 4; jn++)
                    mma_bf16(sacc[nc * 4 + jn], ql[s], bh4[jn]);
            }
        }

        if (j >= 2 * iblk) {
            int row0 = m0 + wm * 16 + l4;
            #pragma unroll
            for (int nt = 0; nt < 8; nt++) {
                int col = j * 64 + nt * 8 + 2 * lk;
                if (col     > row0)     sacc[nt][0] = -1e30f;
                if (col + 1 > row0)     sacc[nt][1] = -1e30f;
                if (col     > row0 + 8) sacc[nt][2] = -1e30f;
                if (col + 1 > row0 + 8) sacc[nt][3] = -1e30f;
            }
        }

        float mx0 = -1e30f, mx1 = -1e30f;
        #pragma unroll
        for (int nt = 0; nt < 8; nt++) {
            mx0 = fmaxf(mx0, fmaxf(sacc[nt][0], sacc[nt][1]));
            mx1 = fmaxf(mx1, fmaxf(sacc[nt][2], sacc[nt][3]));
        }
        mx0 = fmaxf(mx0, __shfl_xor_sync(0xffffffffu, mx0, 1));
        mx0 = fmaxf(mx0, __shfl_xor_sync(0xffffffffu, mx0, 2));
        mx1 = fmaxf(mx1, __shfl_xor_sync(0xffffffffu, mx1, 1));
        mx1 = fmaxf(mx1, __shfl_xor_sync(0xffffffffu, mx1, 2));

        float mn0 = fmaxf(mr0, mx0), mn1 = fmaxf(mr1, mx1);
        float al0 = exp2q((mr0 - mn0) * L2E);
        float al1 = exp2q((mr1 - mn1) * L2E);
        mr0 = mn0; mr1 = mn1;
        float mnl0 = mn0 * L2E, mnl1 = mn1 * L2E;

        unsigned ph01[8], ph23[8];
        float rs0 = 0.f, rs1 = 0.f;
        #pragma unroll
        for (int nt = 0; nt < 8; nt++) {
            float p0 = exp2q(fmaf(sacc[nt][0], L2E, -mnl0));
            float p1 = exp2q(fmaf(sacc[nt][1], L2E, -mnl0));
            float p2 = exp2q(fmaf(sacc[nt][2], L2E, -mnl1));
            float p3 = exp2q(fmaf(sacc[nt][3], L2E, -mnl1));
            rs0 += p0 + p1; rs1 += p2 + p3;
            ph01[nt] = pack_h2(__float2half_rn(p0), __float2half_rn(p1));
            ph23[nt] = pack_h2(__float2half_rn(p2), __float2half_rn(p3));
        }
        rs0 += __shfl_xor_sync(0xffffffffu, rs0, 1);
        rs0 += __shfl_xor_sync(0xffffffffu, rs0, 2);
        rs1 += __shfl_xor_sync(0xffffffffu, rs1, 1);
        rs1 += __shfl_xor_sync(0xffffffffu, rs1, 2);
        lr0 = lr0 * al0 + rs0;
        lr1 = lr1 * al1 + rs1;

        #pragma unroll
        for (int nt = 0; nt < 16; nt++) {
            oacc[nt][0] *= al0; oacc[nt][1] *= al0;
            oacc[nt][2] *= al1; oacc[nt][3] *= al1;
        }

        #pragma unroll
        for (int t = 0; t < 4; t++) {
            unsigned pa[4];
            pa[0] = ph01[2 * t];
            pa[1] = ph23[2 * t];
            pa[2] = ph01[2 * t + 1];
            pa[3] = ph23[2 * t + 1];
            #pragma unroll
            for (int nc = 0; nc < 4; nc++) {
                unsigned bh4[4][2], bl4[4][2];
                #pragma unroll
                for (int jn = 0; jn < 4; jn++) {
                    int vr = (8 * t + lk) * VPP + (nc * 4 + jn) * 8 + l4;
                    bh4[jn][0] = Vph[vr];
                    bh4[jn][1] = Vph[vr + 4 * VPP];
                    bl4[jn][0] = Vpl[vr];
                    bl4[jn][1] = Vpl[vr + 4 * VPP];
                }
                #pragma unroll
                for (int jn = 0; jn < 4; jn++)
                    mma_f16_f32(oacc[nc * 4 + jn], pa, bh4[jn]);
                #pragma unroll
                for (int jn = 0; jn < 4; jn++)
                    mma_f16_f32(oacc[nc * 4 + jn], pa, bl4[jn]);
            }
        }
        __syncthreads();
    }

    float il0 = 1.f / lr0, il1 = 1.f / lr1;
    int row0 = m0 + wm * 16 + l4;
    #pragma unroll
    for (int nt = 0; nt < 16; nt++) {
        int col = h * DHEAD + nt * 8 + 2 * lk;
        float2 o0 = make_float2(oacc[nt][0] * il0, oacc[nt][1] * il0);
        float2 o1 = make_float2(oacc[nt][2] * il1, oacc[nt][3] * il1);
        *(float2*)(o + (rowbase + row0) * EMB + col)     = o0;
        *(float2*)(o + (rowbase + row0 + 8) * EMB + col) = o1;
    }
}

// ---------------------------------------------------------------------------
extern "C" void kernel_launch(void* const* d_in, const int* in_sizes, int n_in,
                              void* d_out, int out_size)
{
    const float* x    = (const float*)d_in[0];
    const float* mask = (const float*)d_in[1];
    const float* Wq = (const float*)d_in[2];  const float* bq = (const float*)d_in[3];
    const float* Aq = (const float*)d_in[4];  const float* Bq = (const float*)d_in[5];
    const float* Cq = (const float*)d_in[6];  const float* Rq = (const float*)d_in[7];
    const float* Wk = (const float*)d_in[8];  const float* bk = (const float*)d_in[9];
    const float* Ak = (const float*)d_in[10]; const float* Bk = (const float*)d_in[11];
    const float* Ck = (const float*)d_in[12]; const float* Rk = (const float*)d_in[13];
    const float* Wv = (const float*)d_in[14]; const float* bv = (const float*)d_in[15];
    const float* Av = (const float*)d_in[16]; const float* Bv = (const float*)d_in[17];
    const float* Cv = (const float*)d_in[18]; const float* Rv = (const float*)d_in[19];
    const float* Wo = (const float*)d_in[20]; const float* Ao = (const float*)d_in[21];
    const float* Bo = (const float*)d_in[22]; const float* Co = (const float*)d_in[23];
    const float* Ro = (const float*)d_in[24];

    float *q, *k, *v, *att, *hx;
    unsigned *kph, *kpl, *vph, *vpl;
    cudaGetSymbolAddress((void**)&q,   g_q);
    cudaGetSymbolAddress((void**)&k,   g_k);
    cudaGetSymbolAddress((void**)&v,   g_v);
    cudaGetSymbolAddress((void**)&att, g_att);
    cudaGetSymbolAddress((void**)&hx,  g_haux);
    cudaGetSymbolAddress((void**)&kph, g_kph);
    cudaGetSymbolAddress((void**)&kpl, g_kpl);
    cudaGetSymbolAddress((void**)&vph, g_vph);
    cudaGetSymbolAddress((void**)&vpl, g_vpl);

    float* hq = hx;
    float* hk = hx + (size_t)ROWS * 96;
    float* hv = hx + (size_t)ROWS * 96 * 2;
    float* ho = hx + (size_t)ROWS * 96 * 3;

    cudaFuncSetAttribute(flash_mma,
                         cudaFuncAttributeMaxDynamicSharedMemorySize, FA2_SMEM);

    dim3 ggrid(EMB / 128, ROWS / 128);   // (16, 32)

    aux_mma<<<dim3(3, ROWS / 128), 256>>>(x, mask, Aq, Cq, Ak, Ck, Av, Cv, hq, hk, hv);
    gemm_mma<<<ggrid, 256>>>(x, hq, Wq, Bq, Rq, bq, q);
    gemm_mma<<<ggrid, 256>>>(x, hk, Wk, Bk, Rk, bk, k);
    gemm_mma<<<ggrid, 256>>>(x, hv, Wv, Bv, Rv, bv, v);
    rope_pack<<<(ROWS * NHEAD * 32 + 255) / 256, 256>>>(q, k, kph, kpl);
    vpack<<<(32 * 1024 * 128 + 255) / 256, 256>>>(v, vph, vpl);
    flash_mma<<<dim3(SEQ / 128, BATCH * NHEAD), 256, FA2_SMEM>>>(q, kph, kpl, vph, vpl, att);
    aux_mma<<<dim3(1, ROWS / 128), 256>>>(att, mask, Ao, Co, Ao, Co, Ao, Co, ho, ho, ho);
    gemm_mma<<<ggrid, 256>>>(att, ho, Wo, Bo, Ro, nullptr, (float*)d_out);
}

// round 13
// speedup vs baseline: 1.1593x; 1.1593x over previous
#include <cuda_runtime.h>
#include <cuda_bf16.h>
#include <cuda_fp16.h>
#include <cstdint>
#include <math.h>

#define BATCH 2
#define SEQ   2048
#define EMB   2048
#define NHEAD 16
#define DHEAD 128
#define NEXP_ 64
#define RLORA 32
#define ROWS  4096
#define KAUG  2144

// ---------------- scratch ----------------
__device__ float g_q[(size_t)ROWS * EMB];
__device__ float g_k[(size_t)ROWS * EMB];
__device__ float g_v[(size_t)ROWS * EMB];
__device__ float g_att[(size_t)ROWS * EMB];
__device__ float g_haux[4][(size_t)ROWS * 96];
__device__ unsigned g_kph[(size_t)32 * 2048 * 64];
__device__ unsigned g_kpl[(size_t)32 * 2048 * 64];
__device__ unsigned g_vph[(size_t)32 * 1024 * 128];
__device__ unsigned g_vpl[(size_t)32 * 1024 * 128];

// ---------------- helpers ----------------
__device__ __forceinline__ unsigned pack_bf2(__nv_bfloat16 a, __nv_bfloat16 b) {
    return (unsigned)__bfloat16_as_ushort(a) | ((unsigned)__bfloat16_as_ushort(b) << 16);
}
__device__ __forceinline__ void split_bf(float x, __nv_bfloat16& hi, __nv_bfloat16& lo) {
    hi = __float2bfloat16_rn(x);
    lo = __float2bfloat16_rn(x - __bfloat162float(hi));
}
__device__ __forceinline__ unsigned pack_h2(__half a, __half b) {
    __half2 t = __halves2half2(a, b);
    return *(unsigned*)&t;
}
__device__ __forceinline__ void split_h_plain(float x, __half& hi, __half& lo) {
    hi = __float2half_rn(x);
    lo = __float2half_rn(x - __half2float(hi));
}
__device__ __forceinline__ void mma_bf16(float* c, const unsigned* a, const unsigned* b) {
    asm volatile(
        "mma.sync.aligned.m16n8k16.row.col.f32.bf16.bf16.f32 "
        "{%0,%1,%2,%3}, {%4,%5,%6,%7}, {%8,%9}, {%0,%1,%2,%3};"
        : "+f"(c[0]), "+f"(c[1]), "+f"(c[2]), "+f"(c[3])
        : "r"(a[0]), "r"(a[1]), "r"(a[2]), "r"(a[3]), "r"(b[0]), "r"(b[1]));
}
__device__ __forceinline__ void mma_f16_f32(float* c, const unsigned* a, const unsigned* b) {
    asm volatile(
        "mma.sync.aligned.m16n8k16.row.col.f32.f16.f16.f32 "
        "{%0,%1,%2,%3}, {%4,%5,%6,%7}, {%8,%9}, {%0,%1,%2,%3};"
        : "+f"(c[0]), "+f"(c[1]), "+f"(c[2]), "+f"(c[3])
        : "r"(a[0]), "r"(a[1]), "r"(a[2]), "r"(a[3]), "r"(b[0]), "r"(b[1]));
}

#define L2E 1.4426950408889634f

__device__ __forceinline__ float exp2q(float t) {
    t = fmaxf(t, -126.f);
    float z = t + 12582912.f;               // 1.5*2^23
    int ni = __float_as_int(z) - 0x4B400000;
    float r = t - (z - 12582912.f);
    float p = 1.3333558146e-3f;
    p = fmaf(p, r, 9.6181291876e-3f);
    p = fmaf(p, r, 5.5504108665e-2f);
    p = fmaf(p, r, 2.4022650696e-1f);
    p = fmaf(p, r, 6.9314718056e-1f);
    p = fmaf(p, r, 1.0f);
    return p * __int_as_float((ni + 127) << 23);
}

// ---------------------------------------------------------------------------
// aux GEMM on tensor cores (bf16 split, 3-term): unchanged from R11.
// ---------------------------------------------------------------------------
__global__ __launch_bounds__(256) void aux_mma(
    const float* __restrict__ act, const float* __restrict__ mask,
    const float* __restrict__ A0, const float* __restrict__ C0,
    const float* __restrict__ A1, const float* __restrict__ C1,
    const float* __restrict__ A2, const float* __restrict__ C2,
    float* __restrict__ h0, float* __restrict__ h1, float* __restrict__ h2)
{
    __shared__ unsigned Ah[128][20], Al[128][20];
    __shared__ unsigned Bh[96][20],  Blo[96][20];

    const int proj = blockIdx.x;
    const int m0 = blockIdx.y * 128;
    const float* A = (proj == 0) ? A0 : ((proj == 1) ? A1 : A2);
    const float* C = (proj == 0) ? C0 : ((proj == 1) ? C1 : C2);
    float* hout    = (proj == 0) ? h0 : ((proj == 1) ? h1 : h2);

    const int tid = threadIdx.x;
    const int lane = tid & 31, wid = tid >> 5;
    const int l4 = lane >> 2, lk = lane & 3;
    const int warp_m = wid & 3, warp_n = wid >> 2;

    float c[2][6][4];
    #pragma unroll
    for (int mt = 0; mt < 2; mt++)
        #pragma unroll
        for (int nt = 0; nt < 6; nt++)
            #pragma unroll
            for (int i = 0; i < 4; i++) c[mt][nt][i] = 0.f;

    for (int k0 = 0; k0 < EMB; k0 += 32) {
        #pragma unroll
        for (int i = 0; i < 4; i++) {
            int lin = tid + 256 * i;
            int r = lin >> 3, c4 = (lin & 7) << 2;
            float4 va = *(const float4*)(act + (size_t)(m0 + r) * EMB + k0 + c4);
            __nv_bfloat16 hx, lx, hy, ly, hz, lz, hw, lw;
            split_bf(va.x, hx, lx); split_bf(va.y, hy, ly);
            split_bf(va.z, hz, lz); split_bf(va.w, hw, lw);
            int wofs = c4 >> 1;
            *(uint2*)&Ah[r][wofs] = make_uint2(pack_bf2(hx, hy), pack_bf2(hz, hw));
            *(uint2*)&Al[r][wofs] = make_uint2(pack_bf2(lx, ly), pack_bf2(lz, lw));
        }
        #pragma unroll
        for (int i = 0; i < 3; i++) {
            int lin = tid + 256 * i;
            if (lin < 768) {
                int r = lin >> 3, c4 = (lin & 7) << 2;
                const float* src = (r < 32) ? (A + (size_t)r * EMB)
                                            : (C + (size_t)(r - 32) * EMB);
                float4 vb = *(const float4*)(src + k0 + c4);
                __nv_bfloat16 hx, lx, hy, ly, hz, lz, hw, lw;
                split_bf(vb.x, hx, lx); split_bf(vb.y, hy, ly);
                split_bf(vb.z, hz, lz); split_bf(vb.w, hw, lw);
                int wofs = c4 >> 1;
                *(uint2*)&Bh[r][wofs]  = make_uint2(pack_bf2(hx, hy), pack_bf2(hz, hw));
                *(uint2*)&Blo[r][wofs] = make_uint2(pack_bf2(lx, ly), pack_bf2(lz, lw));
            }
        }
        __syncthreads();

        #pragma unroll
        for (int ks = 0; ks < 2; ks++) {
            const int kw = ks * 8;
            unsigned ah[2][4], al[2][4];
            #pragma unroll
            for (int mt = 0; mt < 2; mt++) {
                int rb = warp_m * 32 + mt * 16 + l4;
                ah[mt][0] = Ah[rb][kw + lk];
                ah[mt][1] = Ah[rb + 8][kw + lk];
                ah[mt][2] = Ah[rb][kw + 4 + lk];
                ah[mt][3] = Ah[rb + 8][kw + 4 + lk];
                al[mt][0] = Al[rb][kw + lk];
                al[mt][1] = Al[rb + 8][kw + lk];
                al[mt][2] = Al[rb][kw + 4 + lk];
                al[mt][3] = Al[rb + 8][kw + 4 + lk];
            }
            #pragma unroll
            for (int nt = 0; nt < 6; nt++) {
                int cb = warp_n * 48 + nt * 8 + l4;
                unsigned bh[2], bl[2];
                bh[0] = Bh[cb][kw + lk];
                bh[1] = Bh[cb][kw + 4 + lk];
                bl[0] = Blo[cb][kw + lk];
                bl[1] = Blo[cb][kw + 4 + lk];
                #pragma unroll
                for (int mt = 0; mt < 2; mt++) {
                    mma_bf16(c[mt][nt], ah[mt], bh);
                    mma_bf16(c[mt][nt], ah[mt], bl);
                    mma_bf16(c[mt][nt], al[mt], bh);
                }
            }
        }
        __syncthreads();
    }

    #pragma unroll
    for (int mt = 0; mt < 2; mt++) {
        int r0 = m0 + warp_m * 32 + mt * 16 + l4;
        #pragma unroll
        for (int nt = 0; nt < 6; nt++) {
            int u = warp_n * 48 + nt * 8 + 2 * lk;
            #pragma unroll
            for (int half = 0; half < 2; half++) {
                int row = r0 + half * 8;
                float v0 = c[mt][nt][half * 2 + 0];
                float v1 = c[mt][nt][half * 2 + 1];
                float s0 = v0 / (1.f + __expf(-v0));
                float s1 = v1 / (1.f + __expf(-v1));
                if (u >= 32)     s0 *= mask[(size_t)row * NEXP_ + (u - 32)];
                if (u + 1 >= 32) s1 *= mask[(size_t)row * NEXP_ + (u + 1 - 32)];
                hout[(size_t)row * 96 + u]     = s0;
                hout[(size_t)row * 96 + u + 1] = s1;
            }
        }
    }
}

// ---------------------------------------------------------------------------
// K-augmented GEMM, 2-term fp16 split: A = hi+lo fp16, W truncated fp16.
// D = hi_a*w + lo_a*w  (2 MMAs per tile instead of 3).
// Block 128x128x32, 8 warps (4m x 2n), warp tile 32x64.
// ---------------------------------------------------------------------------
#define GP 20

__global__ __launch_bounds__(256, 2) void gemm_2t(
    const float* __restrict__ act, const float* __restrict__ haux,
    const float* __restrict__ Wd,  const float* __restrict__ Bl,
    const float* __restrict__ Rr,  const float* __restrict__ bias,
    float* __restrict__ out)
{
    __shared__ unsigned As_hi[128][GP], As_lo[128][GP];
    __shared__ unsigned Bs_h[128][GP];

    const int tid = threadIdx.x;
    const int lane = tid & 31, wid = tid >> 5;
    const int l4 = lane >> 2, lk = lane & 3;
    const int warp_m = wid & 3, warp_n = wid >> 2;
    const int m0 = blockIdx.y * 128, n0 = blockIdx.x * 128;

    float c[2][8][4];
    #pragma unroll
    for (int mt = 0; mt < 2; mt++)
        #pragma unroll
        for (int nt = 0; nt < 8; nt++)
            #pragma unroll
            for (int i = 0; i < 4; i++) c[mt][nt][i] = 0.f;

    for (int k0 = 0; k0 < KAUG; k0 += 32) {
        const float* asrc; int lda, kof;
        if (k0 < EMB) { asrc = act;  lda = EMB; kof = k0; }
        else          { asrc = haux; lda = 96;  kof = k0 - EMB; }

        const float* wsrc; int ldw, kofw;
        if (k0 < EMB)              { wsrc = Wd; ldw = EMB;   kofw = k0; }
        else if (k0 < EMB + RLORA) { wsrc = Bl; ldw = RLORA; kofw = k0 - EMB; }
        else                       { wsrc = Rr; ldw = NEXP_; kofw = k0 - EMB - RLORA; }

        // A: fp16 hi/lo
        #pragma unroll
        for (int i = 0; i < 4; i++) {
            int lin = tid + 256 * i;
            int r = lin >> 3, c4 = (lin & 7) << 2;
            float4 va = *(const float4*)(asrc + (size_t)(m0 + r) * lda + kof + c4);
            __half hx, lx, hy, ly, hz, lz, hw, lw;
            split_h_plain(va.x, hx, lx); split_h_plain(va.y, hy, ly);
            split_h_plain(va.z, hz, lz); split_h_plain(va.w, hw, lw);
            int wofs = c4 >> 1;
            *(uint2*)&As_hi[r][wofs] = make_uint2(pack_h2(hx, hy), pack_h2(hz, hw));
            *(uint2*)&As_lo[r][wofs] = make_uint2(pack_h2(lx, ly), pack_h2(lz, lw));
        }
        // B: fp16 truncated (single plane)
        #pragma unroll
        for (int i = 0; i < 4; i++) {
            int lin = tid + 256 * i;
            int r = lin >> 3, c4 = (lin & 7) << 2;
            float4 vb = *(const float4*)(wsrc + (size_t)(n0 + r) * ldw + kofw + c4);
            int wofs = c4 >> 1;
            *(uint2*)&Bs_h[r][wofs] = make_uint2(
                pack_h2(__float2half_rn(vb.x), __float2half_rn(vb.y)),
                pack_h2(__float2half_rn(vb.z), __float2half_rn(vb.w)));
        }
        __syncthreads();

        #pragma unroll
        for (int ks = 0; ks < 2; ks++) {
            const int kw = ks * 8;
            unsigned a_hi[2][4], a_lo[2][4];
            #pragma unroll
            for (int mt = 0; mt < 2; mt++) {
                int rb = warp_m * 32 + mt * 16 + l4;
                a_hi[mt][0] = As_hi[rb][kw + lk];
                a_hi[mt][1] = As_hi[rb + 8][kw + lk];
                a_hi[mt][2] = As_hi[rb][kw + 4 + lk];
                a_hi[mt][3] = As_hi[rb + 8][kw + 4 + lk];
                a_lo[mt][0] = As_lo[rb][kw + lk];
                a_lo[mt][1] = As_lo[rb + 8][kw + lk];
                a_lo[mt][2] = As_lo[rb][kw + 4 + lk];
                a_lo[mt][3] = As_lo[rb + 8][kw + 4 + lk];
            }
            #pragma unroll
            for (int nt = 0; nt < 8; nt++) {
                int cb = warp_n * 64 + nt * 8 + l4;
                unsigned bh[2];
                bh[0] = Bs_h[cb][kw + lk];
                bh[1] = Bs_h[cb][kw + 4 + lk];
                #pragma unroll
                for (int mt = 0; mt < 2; mt++) {
                    mma_f16_f32(c[mt][nt], a_hi[mt], bh);
                    mma_f16_f32(c[mt][nt], a_lo[mt], bh);
                }
            }
        }
        __syncthreads();
    }

    float2 bv[8];
    #pragma unroll
    for (int nt = 0; nt < 8; nt++) {
        int col = n0 + warp_n * 64 + nt * 8 + 2 * lk;
        if (bias) bv[nt] = *(const float2*)(bias + col);
        else      bv[nt] = make_float2(0.f, 0.f);
    }
    #pragma unroll
    for (int mt = 0; mt < 2; mt++) {
        int r0 = m0 + warp_m * 32 + mt * 16 + l4;
        #pragma unroll
        for (int nt = 0; nt < 8; nt++) {
            int col = n0 + warp_n * 64 + nt * 8 + 2 * lk;
            float2 o0 = make_float2(c[mt][nt][0] + bv[nt].x, c[mt][nt][1] + bv[nt].y);
            float2 o1 = make_float2(c[mt][nt][2] + bv[nt].x, c[mt][nt][3] + bv[nt].y);
            *(float2*)(out + (size_t)r0 * EMB + col)       = o0;
            *(float2*)(out + (size_t)(r0 + 8) * EMB + col) = o1;
        }
    }
}

// ---------------------------------------------------------------------------
// rope_pack: rope q in-place (fp32); rope k -> packed bf16 hi/lo
// ---------------------------------------------------------------------------
__global__ void rope_pack(float* __restrict__ q, const float* __restrict__ k,
                          unsigned* __restrict__ kph, unsigned* __restrict__ kpl)
{
    int idx = blockIdx.x * blockDim.x + threadIdx.x;
    if (idx >= ROWS * NHEAD * 32) return;
    int jj  = idx & 31;
    int h   = (idx >> 5) & 15;
    int row = idx >> 9;
    int s   = row & (SEQ - 1);
    int b   = row >> 11;

    float sn[2], cs[2];
    #pragma unroll
    for (int t = 0; t < 2; t++) {
        int d = 2 * jj + t;
        float e = (float)(2 * d) * (1.0f / 128.0f);
        float inv = powf(10000.0f, -e);
        sincosf((float)s * inv, &sn[t], &cs[t]);
    }

    size_t base = (size_t)row * EMB + h * DHEAD;
    float qlo[2], qhi2[2], klo[2], khi2[2];
    #pragma unroll
    for (int t = 0; t < 2; t++) {
        int d = 2 * jj + t;
        float x1 = q[base + d], x2 = q[base + d + 64];
        qlo[t]  = x1 * cs[t] - x2 * sn[t];
        qhi2[t] = x2 * cs[t] + x1 * sn[t];
        float y1 = k[base + d], y2 = k[base + d + 64];
        klo[t]  = y1 * cs[t] - y2 * sn[t];
        khi2[t] = y2 * cs[t] + y1 * sn[t];
    }
    #pragma unroll
    for (int t = 0; t < 2; t++) {
        q[base + 2 * jj + t]      = qlo[t];
        q[base + 2 * jj + t + 64] = qhi2[t];
    }
    int bh = b * NHEAD + h;
    size_t kbase = ((size_t)bh * SEQ + s) * 64;
    __nv_bfloat16 h0, l0, h1, l1;
    split_bf(klo[0], h0, l0); split_bf(klo[1], h1, l1);
    kph[kbase + jj] = pack_bf2(h0, h1);
    kpl[kbase + jj] = pack_bf2(l0, l1);
    split_bf(khi2[0], h0, l0); split_bf(khi2[1], h1, l1);
    kph[kbase + jj + 32] = pack_bf2(h0, h1);
    kpl[kbase + jj + 32] = pack_bf2(l0, l1);
}

// ---------------------------------------------------------------------------
// vpack: V fp16 hi/lo packed along k-pairs
// ---------------------------------------------------------------------------
__global__ void vpack(const float* __restrict__ v,
                      unsigned* __restrict__ vph, unsigned* __restrict__ vpl)
{
    int idx = blockIdx.x * blockDim.x + threadIdx.x;
    if (idx >= 32 * 1024 * 128) return;
    int nn = idx & 127;
    int kw = (idx >> 7) & 1023;
    int bh = idx >> 17;
    int b = bh >> 4, h = bh & 15;
    size_t addr = ((size_t)(b * SEQ + 2 * kw)) * EMB + h * DHEAD + nn;
    float v0 = v[addr], v1 = v[addr + EMB];
    __half h0, l0, h1, l1;
    split_h_plain(v0, h0, l0); split_h_plain(v1, h1, l1);
    vph[idx] = pack_h2(h0, h1);
    vpl[idx] = pack_h2(l0, l1);
}

// ---------------------------------------------------------------------------
// Flash attention (unchanged from R11): QK 3-term bf16, PV 2-term fp16,
// poly exp on FMA pipe.
// ---------------------------------------------------------------------------
#define KPP 68
#define VPP 136
#define FA2_SMEM ((64 * KPP * 2 + 32 * VPP * 2) * 4)

__global__ __launch_bounds__(256) void flash_mma(
    const float* __restrict__ q,
    const unsigned* __restrict__ kph, const unsigned* __restrict__ kpl,
    const unsigned* __restrict__ vph, const unsigned* __restrict__ vpl,
    float* __restrict__ o)
{
    extern __shared__ unsigned sw_[];
    unsigned* Kph = sw_;
    unsigned* Kpl = Kph + 64 * KPP;
    unsigned* Vph = Kpl + 64 * KPP;
    unsigned* Vpl = Vph + 32 * VPP;

    const int tid = threadIdx.x;
    const int lane = tid & 31, wm = tid >> 5;
    const int l4 = lane >> 2, lk = lane & 3;
    const int iblk = (int)gridDim.x - 1 - (int)blockIdx.x;
    const int bh = blockIdx.y;
    const int b = bh >> 4, h = bh & 15;
    const size_t rowbase = (size_t)b * SEQ;
    const int m0 = iblk * 128;
    const float scale = 0.08838834764831845f;

    unsigned qh[8][4], ql[8][4];
    {
        const int r0 = m0 + wm * 16 + l4;
        #pragma unroll
        for (int s = 0; s < 8; s++) {
            #pragma unroll
            for (int f = 0; f < 4; f++) {
                int r = r0 + ((f & 1) ? 8 : 0);
                int d = 16 * s + 2 * lk + ((f & 2) ? 8 : 0);
                float2 qv = *(const float2*)(q + (rowbase + r) * EMB + h * DHEAD + d);
                float x = qv.x * scale, y = qv.y * scale;
                __nv_bfloat16 hx, lx, hy, ly;
                split_bf(x, hx, lx); split_bf(y, hy, ly);
                qh[s][f] = pack_bf2(hx, hy);
                ql[s][f] = pack_bf2(lx, ly);
            }
        }
    }

    float mr0 = -1e30f, mr1 = -1e30f, lr0 = 0.f, lr1 = 0.f;
    float oacc[16][4];
    #pragma unroll
    for (int nt = 0; nt < 16; nt++)
        #pragma unroll
        for (int i = 0; i < 4; i++) oacc[nt][i] = 0.f;

    const size_t kbase = (size_t)bh * SEQ * 64;
    const size_t vbase = (size_t)bh * 1024 * 128;

    const int ntiles = 2 * iblk + 2;
    for (int j = 0; j < ntiles; j++) {
        #pragma unroll
        for (int i = 0; i < 4; i++) {
            int lin = tid + 256 * i;
            int r = lin >> 4, c4 = (lin & 15) << 2;
            size_t src = kbase + (size_t)(j * 64 + r) * 64 + c4;
            *(uint4*)&Kph[r * KPP + c4] = *(const uint4*)(kph + src);
            *(uint4*)&Kpl[r * KPP + c4] = *(const uint4*)(kpl + src);
        }
        #pragma unroll
        for (int i = 0; i < 4; i++) {
            int lin = tid + 256 * i;
            int r = lin >> 5, c4 = (lin & 31) << 2;
            size_t src = vbase + (size_t)(j * 32 + r) * 128 + c4;
            *(uint4*)&Vph[r * VPP + c4] = *(const uint4*)(vph + src);
            *(uint4*)&Vpl[r * VPP + c4] = *(const uint4*)(vpl + src);
        }
        __syncthreads();

        float sacc[8][4];
        #pragma unroll
        for (int nt = 0; nt < 8; nt++)
            #pragma unroll
            for (int i = 0; i < 4; i++) sacc[nt][i] = 0.f;

        #pragma unroll
        for (int s = 0; s < 8; s++) {
            #pragma unroll
            for (int nt = 0; nt < 8; nt++) {
                int kr = (nt * 8 + l4) * KPP + 8 * s + lk;
                unsigned b_hi[2], b_lo[2];
                b_hi[0] = Kph[kr];
                b_hi[1] = Kph[kr + 4];
                b_lo[0] = Kpl[kr];
                b_lo[1] = Kpl[kr + 4];
                mma_bf16(sacc[nt], qh[s], b_hi);
                mma_bf16(sacc[nt], qh[s], b_lo);
                mma_bf16(sacc[nt], ql[s], b_hi);
            }
        }

        if (j >= 2 * iblk) {
            int row0 = m0 + wm * 16 + l4;
            #pragma unroll
            for (int nt = 0; nt < 8; nt++) {
                int col = j * 64 + nt * 8 + 2 * lk;
                if (col     > row0)     sacc[nt][0] = -1e30f;
                if (col + 1 > row0)     sacc[nt][1] = -1e30f;
                if (col     > row0 + 8) sacc[nt][2] = -1e30f;
                if (col + 1 > row0 + 8) sacc[nt][3] = -1e30f;
            }
        }

        float mx0 = -1e30f, mx1 = -1e30f;
        #pragma unroll
        for (int nt = 0; nt < 8; nt++) {
            mx0 = fmaxf(mx0, fmaxf(sacc[nt][0], sacc[nt][1]));
            mx1 = fmaxf(mx1, fmaxf(sacc[nt][2], sacc[nt][3]));
        }
        mx0 = fmaxf(mx0, __shfl_xor_sync(0xffffffffu, mx0, 1));
        mx0 = fmaxf(mx0, __shfl_xor_sync(0xffffffffu, mx0, 2));
        mx1 = fmaxf(mx1, __shfl_xor_sync(0xffffffffu, mx1, 1));
        mx1 = fmaxf(mx1, __shfl_xor_sync(0xffffffffu, mx1, 2));

        float mn0 = fmaxf(mr0, mx0), mn1 = fmaxf(mr1, mx1);
        float al0 = exp2q((mr0 - mn0) * L2E);
        float al1 = exp2q((mr1 - mn1) * L2E);
        mr0 = mn0; mr1 = mn1;
        float mnl0 = mn0 * L2E, mnl1 = mn1 * L2E;

        unsigned ph01[8], ph23[8];
        float rs0 = 0.f, rs1 = 0.f;
        #pragma unroll
        for (int nt = 0; nt < 8; nt++) {
            float p0 = exp2q(fmaf(sacc[nt][0], L2E, -mnl0));
            float p1 = exp2q(fmaf(sacc[nt][1], L2E, -mnl0));
            float p2 = exp2q(fmaf(sacc[nt][2], L2E, -mnl1));
            float p3 = exp2q(fmaf(sacc[nt][3], L2E, -mnl1));
            rs0 += p0 + p1; rs1 += p2 + p3;
            ph01[nt] = pack_h2(__float2half_rn(p0), __float2half_rn(p1));
            ph23[nt] = pack_h2(__float2half_rn(p2), __float2half_rn(p3));
        }
        rs0 += __shfl_xor_sync(0xffffffffu, rs0, 1);
        rs0 += __shfl_xor_sync(0xffffffffu, rs0, 2);
        rs1 += __shfl_xor_sync(0xffffffffu, rs1, 1);
        rs1 += __shfl_xor_sync(0xffffffffu, rs1, 2);
        lr0 = lr0 * al0 + rs0;
        lr1 = lr1 * al1 + rs1;

        #pragma unroll
        for (int nt = 0; nt < 16; nt++) {
            oacc[nt][0] *= al0; oacc[nt][1] *= al0;
            oacc[nt][2] *= al1; oacc[nt][3] *= al1;
        }

        #pragma unroll
        for (int t = 0; t < 4; t++) {
            unsigned pa[4];
            pa[0] = ph01[2 * t];
            pa[1] = ph23[2 * t];
            pa[2] = ph01[2 * t + 1];
            pa[3] = ph23[2 * t + 1];
            #pragma unroll
            for (int nt = 0; nt < 16; nt++) {
                int vr = (8 * t + lk) * VPP + nt * 8 + l4;
                unsigned b_hi[2], b_lo[2];
                b_hi[0] = Vph[vr];
                b_hi[1] = Vph[vr + 4 * VPP];
                b_lo[0] = Vpl[vr];
                b_lo[1] = Vpl[vr + 4 * VPP];
                mma_f16_f32(oacc[nt], pa, b_hi);
                mma_f16_f32(oacc[nt], pa, b_lo);
            }
        }
        __syncthreads();
    }

    float il0 = 1.f / lr0, il1 = 1.f / lr1;
    int row0 = m0 + wm * 16 + l4;
    #pragma unroll
    for (int nt = 0; nt < 16; nt++) {
        int col = h * DHEAD + nt * 8 + 2 * lk;
        float2 o0 = make_float2(oacc[nt][0] * il0, oacc[nt][1] * il0);
        float2 o1 = make_float2(oacc[nt][2] * il1, oacc[nt][3] * il1);
        *(float2*)(o + (rowbase + row0) * EMB + col)     = o0;
        *(float2*)(o + (rowbase + row0 + 8) * EMB + col) = o1;
    }
}

// ---------------------------------------------------------------------------
extern "C" void kernel_launch(void* const* d_in, const int* in_sizes, int n_in,
                              void* d_out, int out_size)
{
    const float* x    = (const float*)d_in[0];
    const float* mask = (const float*)d_in[1];
    const float* Wq = (const float*)d_in[2];  const float* bq = (const float*)d_in[3];
    const float* Aq = (const float*)d_in[4];  const float* Bq = (const float*)d_in[5];
    const float* Cq = (const float*)d_in[6];  const float* Rq = (const float*)d_in[7];
    const float* Wk = (const float*)d_in[8];  const float* bk = (const float*)d_in[9];
    const float* Ak = (const float*)d_in[10]; const float* Bk = (const float*)d_in[11];
    const float* Ck = (const float*)d_in[12]; const float* Rk = (const float*)d_in[13];
    const float* Wv = (const float*)d_in[14]; const float* bv = (const float*)d_in[15];
    const float* Av = (const float*)d_in[16]; const float* Bv = (const float*)d_in[17];
    const float* Cv = (const float*)d_in[18]; const float* Rv = (const float*)d_in[19];
    const float* Wo = (const float*)d_in[20]; const float* Ao = (const float*)d_in[21];
    const float* Bo = (const float*)d_in[22]; const float* Co = (const float*)d_in[23];
    const float* Ro = (const float*)d_in[24];

    float *q, *k, *v, *att, *hx;
    unsigned *kph, *kpl, *vph, *vpl;
    cudaGetSymbolAddress((void**)&q,   g_q);
    cudaGetSymbolAddress((void**)&k,   g_k);
    cudaGetSymbolAddress((void**)&v,   g_v);
    cudaGetSymbolAddress((void**)&att, g_att);
    cudaGetSymbolAddress((void**)&hx,  g_haux);
    cudaGetSymbolAddress((void**)&kph, g_kph);
    cudaGetSymbolAddress((void**)&kpl, g_kpl);
    cudaGetSymbolAddress((void**)&vph, g_vph);
    cudaGetSymbolAddress((void**)&vpl, g_vpl);

    float* hq = hx;
    float* hk = hx + (size_t)ROWS * 96;
    float* hv = hx + (size_t)ROWS * 96 * 2;
    float* ho = hx + (size_t)ROWS * 96 * 3;

    cudaFuncSetAttribute(flash_mma,
                         cudaFuncAttributeMaxDynamicSharedMemorySize, FA2_SMEM);

    dim3 ggrid(EMB / 128, ROWS / 128);   // (16, 32)

    aux_mma<<<dim3(3, ROWS / 128), 256>>>(x, mask, Aq, Cq, Ak, Ck, Av, Cv, hq, hk, hv);
    gemm_2t<<<ggrid, 256>>>(x, hq, Wq, Bq, Rq, bq, q);
    gemm_2t<<<ggrid, 256>>>(x, hk, Wk, Bk, Rk, bk, k);
    gemm_2t<<<ggrid, 256>>>(x, hv, Wv, Bv, Rv, bv, v);
    rope_pack<<<(ROWS * NHEAD * 32 + 255) / 256, 256>>>(q, k, kph, kpl);
    vpack<<<(32 * 1024 * 128 + 255) / 256, 256>>>(v, vph, vpl);
    flash_mma<<<dim3(SEQ / 128, BATCH * NHEAD), 256, FA2_SMEM>>>(q, kph, kpl, vph, vpl, att);
    aux_mma<<<dim3(1, ROWS / 128), 256>>>(att, mask, Ao, Co, Ao, Co, Ao, Co, ho, ho, ho);
    gemm_2t<<<ggrid, 256>>>(att, ho, Wo, Bo, Ro, nullptr, (float*)d_out);
}

// round 14
// speedup vs baseline: 1.2524x; 1.0803x over previous
#include <cuda_runtime.h>
#include <cuda_bf16.h>
#include <cuda_fp16.h>
#include <cstdint>
#include <math.h>

#define BATCH 2
#define SEQ   2048
#define EMB   2048
#define NHEAD 16
#define DHEAD 128
#define NEXP_ 64
#define RLORA 32
#define ROWS  4096
#define KAUG  2144
#define NCH2  67          // K chunks of 32

// ---------------- scratch ----------------
__device__ float g_q[(size_t)ROWS * EMB];
__device__ float g_k[(size_t)ROWS * EMB];
__device__ float g_v[(size_t)ROWS * EMB];
__device__ float g_att[(size_t)ROWS * EMB];
__device__ __half g_xh[(size_t)ROWS * EMB];
__device__ __half g_xl[(size_t)ROWS * EMB];
__device__ __half g_hh[4][(size_t)ROWS * 96];
__device__ __half g_hl[4][(size_t)ROWS * 96];
__device__ __half g_w16[(size_t)4 * 2048 * KAUG];
__device__ unsigned g_kph[(size_t)32 * 2048 * 64];
__device__ unsigned g_kpl[(size_t)32 * 2048 * 64];
__device__ unsigned g_vph[(size_t)32 * 1024 * 128];
__device__ unsigned g_vpl[(size_t)32 * 1024 * 128];

// ---------------- helpers ----------------
__device__ __forceinline__ unsigned pack_bf2(__nv_bfloat16 a, __nv_bfloat16 b) {
    return (unsigned)__bfloat16_as_ushort(a) | ((unsigned)__bfloat16_as_ushort(b) << 16);
}
__device__ __forceinline__ void split_bf(float x, __nv_bfloat16& hi, __nv_bfloat16& lo) {
    hi = __float2bfloat16_rn(x);
    lo = __float2bfloat16_rn(x - __bfloat162float(hi));
}
__device__ __forceinline__ unsigned pack_h2(__half a, __half b) {
    __half2 t = __halves2half2(a, b);
    return *(unsigned*)&t;
}
__device__ __forceinline__ void split_h_plain(float x, __half& hi, __half& lo) {
    hi = __float2half_rn(x);
    lo = __float2half_rn(x - __half2float(hi));
}
__device__ __forceinline__ void mma_bf16(float* c, const unsigned* a, const unsigned* b) {
    asm volatile(
        "mma.sync.aligned.m16n8k16.row.col.f32.bf16.bf16.f32 "
        "{%0,%1,%2,%3}, {%4,%5,%6,%7}, {%8,%9}, {%0,%1,%2,%3};"
        : "+f"(c[0]), "+f"(c[1]), "+f"(c[2]), "+f"(c[3])
        : "r"(a[0]), "r"(a[1]), "r"(a[2]), "r"(a[3]), "r"(b[0]), "r"(b[1]));
}
__device__ __forceinline__ void mma_f16_f32(float* c, const unsigned* a, const unsigned* b) {
    asm volatile(
        "mma.sync.aligned.m16n8k16.row.col.f32.f16.f16.f32 "
        "{%0,%1,%2,%3}, {%4,%5,%6,%7}, {%8,%9}, {%0,%1,%2,%3};"
        : "+f"(c[0]), "+f"(c[1]), "+f"(c[2]), "+f"(c[3])
        : "r"(a[0]), "r"(a[1]), "r"(a[2]), "r"(a[3]), "r"(b[0]), "r"(b[1]));
}
__device__ __forceinline__ void cp16(unsigned saddr, const void* g) {
    asm volatile("cp.async.cg.shared.global [%0], [%1], 16;" :: "r"(saddr), "l"(g) : "memory");
}
#define CP_COMMIT asm volatile("cp.async.commit_group;\n" ::: "memory")
__device__ __forceinline__ unsigned s2u(const void* p) {
    unsigned a;
    asm("{ .reg .u64 t; cvta.to.shared.u64 t, %1; cvt.u32.u64 %0, t; }" : "=r"(a) : "l"(p));
    return a;
}

#define L2E 1.4426950408889634f
__device__ __forceinline__ float exp2q(float t) {
    t = fmaxf(t, -126.f);
    float z = t + 12582912.f;
    int ni = __float_as_int(z) - 0x4B400000;
    float r = t - (z - 12582912.f);
    float p = 1.3333558146e-3f;
    p = fmaf(p, r, 9.6181291876e-3f);
    p = fmaf(p, r, 5.5504108665e-2f);
    p = fmaf(p, r, 2.4022650696e-1f);
    p = fmaf(p, r, 6.9314718056e-1f);
    p = fmaf(p, r, 1.0f);
    return p * __int_as_float((ni + 127) << 23);
}

// ---------------------------------------------------------------------------
// pack_x: fp32 -> fp16 hi/lo planes
// ---------------------------------------------------------------------------
__global__ void pack_x(const float* __restrict__ src,
                       __half* __restrict__ dh, __half* __restrict__ dl)
{
    size_t i = ((size_t)blockIdx.x * 256 + threadIdx.x) * 8;
    float4 v0 = *(const float4*)(src + i);
    float4 v1 = *(const float4*)(src + i + 4);
    __half h[8], l[8];
    split_h_plain(v0.x, h[0], l[0]); split_h_plain(v0.y, h[1], l[1]);
    split_h_plain(v0.z, h[2], l[2]); split_h_plain(v0.w, h[3], l[3]);
    split_h_plain(v1.x, h[4], l[4]); split_h_plain(v1.y, h[5], l[5]);
    split_h_plain(v1.z, h[6], l[6]); split_h_plain(v1.w, h[7], l[7]);
    uint4 ph = make_uint4(pack_h2(h[0], h[1]), pack_h2(h[2], h[3]),
                          pack_h2(h[4], h[5]), pack_h2(h[6], h[7]));
    uint4 pl = make_uint4(pack_h2(l[0], l[1]), pack_h2(l[2], l[3]),
                          pack_h2(l[4], l[5]), pack_h2(l[6], l[7]));
    *(uint4*)(dh + i) = ph;
    *(uint4*)(dl + i) = pl;
}

// ---------------------------------------------------------------------------
// pack_w16: concat [W | Bl | Rr] rows -> fp16, KAUG stride, 4 projections
// ---------------------------------------------------------------------------
__global__ void pack_w16(
    const float* __restrict__ W0, const float* __restrict__ B0, const float* __restrict__ R0,
    const float* __restrict__ W1, const float* __restrict__ B1, const float* __restrict__ R1,
    const float* __restrict__ W2, const float* __restrict__ B2, const float* __restrict__ R2,
    const float* __restrict__ W3, const float* __restrict__ B3, const float* __restrict__ R3,
    __half* __restrict__ w16)
{
    const int n = blockIdx.x, p = blockIdx.y;
    const float* W = (p == 0) ? W0 : (p == 1) ? W1 : (p == 2) ? W2 : W3;
    const float* Bm = (p == 0) ? B0 : (p == 1) ? B1 : (p == 2) ? B2 : B3;
    const float* Rm = (p == 0) ? R0 : (p == 1) ? R1 : (p == 2) ? R2 : R3;
    __half* d = w16 + ((size_t)p * 2048 + n) * KAUG;

    for (int k = threadIdx.x * 4; k < KAUG; k += 1024) {
        float4 v;
        if (k < EMB)              v = *(const float4*)(W + (size_t)n * EMB + k);
        else if (k < EMB + RLORA) v = *(const float4*)(Bm + (size_t)n * RLORA + (k - EMB));
        else                      v = *(const float4*)(Rm + (size_t)n * NEXP_ + (k - EMB - RLORA));
        uint2 o = make_uint2(pack_h2(__float2half_rn(v.x), __float2half_rn(v.y)),
                             pack_h2(__float2half_rn(v.z), __float2half_rn(v.w)));
        *(uint2*)(d + k) = o;
    }
}

// ---------------------------------------------------------------------------
// aux GEMM (bf16 split, tensor cores); outputs fp16 hi/lo haux planes.
// ---------------------------------------------------------------------------
__global__ __launch_bounds__(256) void aux_mma(
    const float* __restrict__ act, const float* __restrict__ mask,
    const float* __restrict__ A0, const float* __restrict__ C0,
    const float* __restrict__ A1, const float* __restrict__ C1,
    const float* __restrict__ A2, const float* __restrict__ C2,
    __half* __restrict__ hh0, __half* __restrict__ hl0,
    __half* __restrict__ hh1, __half* __restrict__ hl1,
    __half* __restrict__ hh2, __half* __restrict__ hl2)
{
    __shared__ unsigned Ah[128][20], Al[128][20];
    __shared__ unsigned Bh[96][20],  Blo[96][20];

    const int proj = blockIdx.x;
    const int m0 = blockIdx.y * 128;
    const float* A = (proj == 0) ? A0 : ((proj == 1) ? A1 : A2);
    const float* C = (proj == 0) ? C0 : ((proj == 1) ? C1 : C2);
    __half* hh = (proj == 0) ? hh0 : ((proj == 1) ? hh1 : hh2);
    __half* hl = (proj == 0) ? hl0 : ((proj == 1) ? hl1 : hl2);

    const int tid = threadIdx.x;
    const int lane = tid & 31, wid = tid >> 5;
    const int l4 = lane >> 2, lk = lane & 3;
    const int warp_m = wid & 3, warp_n = wid >> 2;

    float c[2][6][4];
    #pragma unroll
    for (int mt = 0; mt < 2; mt++)
        #pragma unroll
        for (int nt = 0; nt < 6; nt++)
            #pragma unroll
            for (int i = 0; i < 4; i++) c[mt][nt][i] = 0.f;

    for (int k0 = 0; k0 < EMB; k0 += 32) {
        #pragma unroll
        for (int i = 0; i < 4; i++) {
            int lin = tid + 256 * i;
            int r = lin >> 3, c4 = (lin & 7) << 2;
            float4 va = *(const float4*)(act + (size_t)(m0 + r) * EMB + k0 + c4);
            __nv_bfloat16 hx, lx, hy, ly, hz, lz, hw, lw;
            split_bf(va.x, hx, lx); split_bf(va.y, hy, ly);
            split_bf(va.z, hz, lz); split_bf(va.w, hw, lw);
            int wofs = c4 >> 1;
            *(uint2*)&Ah[r][wofs] = make_uint2(pack_bf2(hx, hy), pack_bf2(hz, hw));
            *(uint2*)&Al[r][wofs] = make_uint2(pack_bf2(lx, ly), pack_bf2(lz, lw));
        }
        #pragma unroll
        for (int i = 0; i < 3; i++) {
            int lin = tid + 256 * i;
            if (lin < 768) {
                int r = lin >> 3, c4 = (lin & 7) << 2;
                const float* src = (r < 32) ? (A + (size_t)r * EMB)
                                            : (C + (size_t)(r - 32) * EMB);
                float4 vb = *(const float4*)(src + k0 + c4);
                __nv_bfloat16 hx, lx, hy, ly, hz, lz, hw, lw;
                split_bf(vb.x, hx, lx); split_bf(vb.y, hy, ly);
                split_bf(vb.z, hz, lz); split_bf(vb.w, hw, lw);
                int wofs = c4 >> 1;
                *(uint2*)&Bh[r][wofs]  = make_uint2(pack_bf2(hx, hy), pack_bf2(hz, hw));
                *(uint2*)&Blo[r][wofs] = make_uint2(pack_bf2(lx, ly), pack_bf2(lz, lw));
            }
        }
        __syncthreads();

        #pragma unroll
        for (int ks = 0; ks < 2; ks++) {
            const int kw = ks * 8;
            unsigned ah[2][4], al[2][4];
            #pragma unroll
            for (int mt = 0; mt < 2; mt++) {
                int rb = warp_m * 32 + mt * 16 + l4;
                ah[mt][0] = Ah[rb][kw + lk];
                ah[mt][1] = Ah[rb + 8][kw + lk];
                ah[mt][2] = Ah[rb][kw + 4 + lk];
                ah[mt][3] = Ah[rb + 8][kw + 4 + lk];
                al[mt][0] = Al[rb][kw + lk];
                al[mt][1] = Al[rb + 8][kw + lk];
                al[mt][2] = Al[rb][kw + 4 + lk];
                al[mt][3] = Al[rb + 8][kw + 4 + lk];
            }
            #pragma unroll
            for (int nt = 0; nt < 6; nt++) {
                int cb = warp_n * 48 + nt * 8 + l4;
                unsigned bh[2], bl[2];
                bh[0] = Bh[cb][kw + lk];
                bh[1] = Bh[cb][kw + 4 + lk];
                bl[0] = Blo[cb][kw + lk];
                bl[1] = Blo[cb][kw + 4 + lk];
                #pragma unroll
                for (int mt = 0; mt < 2; mt++) {
                    mma_bf16(c[mt][nt], ah[mt], bh);
                    mma_bf16(c[mt][nt], ah[mt], bl);
                    mma_bf16(c[mt][nt], al[mt], bh);
                }
            }
        }
        __syncthreads();
    }

    #pragma unroll
    for (int mt = 0; mt < 2; mt++) {
        int r0 = m0 + warp_m * 32 + mt * 16 + l4;
        #pragma unroll
        for (int nt = 0; nt < 6; nt++) {
            int u = warp_n * 48 + nt * 8 + 2 * lk;
            #pragma unroll
            for (int half = 0; half < 2; half++) {
                int row = r0 + half * 8;
                float v0 = c[mt][nt][half * 2 + 0];
                float v1 = c[mt][nt][half * 2 + 1];
                float s0 = v0 / (1.f + __expf(-v0));
                float s1 = v1 / (1.f + __expf(-v1));
                if (u >= 32)     s0 *= mask[(size_t)row * NEXP_ + (u - 32)];
                if (u + 1 >= 32) s1 *= mask[(size_t)row * NEXP_ + (u + 1 - 32)];
                __half h0, l0, h1, l1;
                split_h_plain(s0, h0, l0);
                split_h_plain(s1, h1, l1);
                hh[(size_t)row * 96 + u]     = h0;
                hh[(size_t)row * 96 + u + 1] = h1;
                hl[(size_t)row * 96 + u]     = l0;
                hl[(size_t)row * 96 + u + 1] = l1;
            }
        }
    }
}

// ---------------------------------------------------------------------------
// Presplit fp16 2-term GEMM with 3-stage cp.async pipeline.
// D = (a_hi + a_lo) * w16. Block 128x128x32, 8 warps, warp 32x64.
// ---------------------------------------------------------------------------
#define PLW   (128 * 20)        // words per plane (pitch 20)
#define STGW  (3 * PLW)         // 3 planes: Ahi, Alo, W
#define GPS_SMEM (3 * STGW * 4) // 3 stages

__global__ __launch_bounds__(256, 2) void gemm_ps(
    const __half* __restrict__ xh, const __half* __restrict__ xl,
    const __half* __restrict__ hh, const __half* __restrict__ hl,
    const __half* __restrict__ w16,
    const float* __restrict__ bias, float* __restrict__ out)
{
    extern __shared__ unsigned smw[];
    const unsigned dsm = s2u(smw);
    const int tid = threadIdx.x;
    const int lane = tid & 31, wid = tid >> 5;
    const int l4 = lane >> 2, lk = lane & 3;
    const int warp_m = wid & 3, warp_n = wid >> 2;
    const int m0 = blockIdx.y * 128, n0 = blockIdx.x * 128;

    float c[2][8][4];
    #pragma unroll
    for (int mt = 0; mt < 2; mt++)
        #pragma unroll
        for (int nt = 0; nt < 8; nt++)
            #pragma unroll
            for (int i = 0; i < 4; i++) c[mt][nt][i] = 0.f;

    // fill rows: thread handles (r, q) pairs: id = tid (+256), r=id>>2, q=id&3
    const int r0f = tid >> 2, q0f = tid & 3;

#define FILLP(STG, CC) do {                                                     \
    int c_ = (CC);                                                              \
    unsigned sb_ = dsm + (STG) * STGW * 4;                                      \
    const __half *pah_, *pal_; int str_;                                        \
    if (c_ < 64) { pah_ = xh + (size_t)m0 * EMB + c_ * 32;                      \
                   pal_ = xl + (size_t)m0 * EMB + c_ * 32; str_ = EMB; }        \
    else         { pah_ = hh + (size_t)m0 * 96 + (c_ - 64) * 32;                \
                   pal_ = hl + (size_t)m0 * 96 + (c_ - 64) * 32; str_ = 96; }   \
    const __half* pw_ = w16 + (size_t)n0 * KAUG + c_ * 32;                      \
    cp16(sb_ + (r0f * 20 + q0f * 4) * 4,        pah_ + (size_t)r0f * str_ + q0f * 8); \
    cp16(sb_ + ((r0f + 64) * 20 + q0f * 4) * 4, pah_ + (size_t)(r0f + 64) * str_ + q0f * 8); \
    cp16(sb_ + (PLW + r0f * 20 + q0f * 4) * 4,        pal_ + (size_t)r0f * str_ + q0f * 8); \
    cp16(sb_ + (PLW + (r0f + 64) * 20 + q0f * 4) * 4, pal_ + (size_t)(r0f + 64) * str_ + q0f * 8); \
    cp16(sb_ + (2 * PLW + r0f * 20 + q0f * 4) * 4,        pw_ + (size_t)(n0 >= 0 ? r0f : r0f) * KAUG + q0f * 8); \
    cp16(sb_ + (2 * PLW + (r0f + 64) * 20 + q0f * 4) * 4, pw_ + (size_t)(r0f + 64) * KAUG + q0f * 8); \
} while (0)

    FILLP(0, 0); CP_COMMIT;
    FILLP(1, 1); CP_COMMIT;

    for (int cc = 0; cc < NCH2; cc++) {
        asm volatile("cp.async.wait_group 1;" ::: "memory");
        __syncthreads();

        int nf = cc + 2;
        if (nf < NCH2) FILLP(nf % 3, nf);
        CP_COMMIT;

        const unsigned* Ahp = smw + (cc % 3) * STGW;
        const unsigned* Alp = Ahp + PLW;
        const unsigned* Wp  = Ahp + 2 * PLW;

        #pragma unroll
        for (int ks = 0; ks < 2; ks++) {
            const int kw = ks * 8;
            unsigned a_hi[2][4], a_lo[2][4];
            #pragma unroll
            for (int mt = 0; mt < 2; mt++) {
                int rb = warp_m * 32 + mt * 16 + l4;
                a_hi[mt][0] = Ahp[rb * 20 + kw + lk];
                a_hi[mt][1] = Ahp[(rb + 8) * 20 + kw + lk];
                a_hi[mt][2] = Ahp[rb * 20 + kw + 4 + lk];
                a_hi[mt][3] = Ahp[(rb + 8) * 20 + kw + 4 + lk];
                a_lo[mt][0] = Alp[rb * 20 + kw + lk];
                a_lo[mt][1] = Alp[(rb + 8) * 20 + kw + lk];
                a_lo[mt][2] = Alp[rb * 20 + kw + 4 + lk];
                a_lo[mt][3] = Alp[(rb + 8) * 20 + kw + 4 + lk];
            }
            #pragma unroll
            for (int nt = 0; nt < 8; nt++) {
                int cb = warp_n * 64 + nt * 8 + l4;
                unsigned bh[2];
                bh[0] = Wp[cb * 20 + kw + lk];
                bh[1] = Wp[cb * 20 + kw + 4 + lk];
                #pragma unroll
                for (int mt = 0; mt < 2; mt++) {
                    mma_f16_f32(c[mt][nt], a_hi[mt], bh);
                    mma_f16_f32(c[mt][nt], a_lo[mt], bh);
                }
            }
        }
    }
#undef FILLP

    float2 bv[8];
    #pragma unroll
    for (int nt = 0; nt < 8; nt++) {
        int col = n0 + warp_n * 64 + nt * 8 + 2 * lk;
        if (bias) bv[nt] = *(const float2*)(bias + col);
        else      bv[nt] = make_float2(0.f, 0.f);
    }
    #pragma unroll
    for (int mt = 0; mt < 2; mt++) {
        int r0 = m0 + warp_m * 32 + mt * 16 + l4;
        #pragma unroll
        for (int nt = 0; nt < 8; nt++) {
            int col = n0 + warp_n * 64 + nt * 8 + 2 * lk;
            float2 o0 = make_float2(c[mt][nt][0] + bv[nt].x, c[mt][nt][1] + bv[nt].y);
            float2 o1 = make_float2(c[mt][nt][2] + bv[nt].x, c[mt][nt][3] + bv[nt].y);
            *(float2*)(out + (size_t)r0 * EMB + col)       = o0;
            *(float2*)(out + (size_t)(r0 + 8) * EMB + col) = o1;
        }
    }
}

// ---------------------------------------------------------------------------
// rope_pack / vpack (unchanged)
// ---------------------------------------------------------------------------
__global__ void rope_pack(float* __restrict__ q, const float* __restrict__ k,
                          unsigned* __restrict__ kph, unsigned* __restrict__ kpl)
{
    int idx = blockIdx.x * blockDim.x + threadIdx.x;
    if (idx >= ROWS * NHEAD * 32) return;
    int jj  = idx & 31;
    int h   = (idx >> 5) & 15;
    int row = idx >> 9;
    int s   = row & (SEQ - 1);
    int b   = row >> 11;

    float sn[2], cs[2];
    #pragma unroll
    for (int t = 0; t < 2; t++) {
        int d = 2 * jj + t;
        float e = (float)(2 * d) * (1.0f / 128.0f);
        float inv = powf(10000.0f, -e);
        sincosf((float)s * inv, &sn[t], &cs[t]);
    }

    size_t base = (size_t)row * EMB + h * DHEAD;
    float qlo[2], qhi2[2], klo[2], khi2[2];
    #pragma unroll
    for (int t = 0; t < 2; t++) {
        int d = 2 * jj + t;
        float x1 = q[base + d], x2 = q[base + d + 64];
        qlo[t]  = x1 * cs[t] - x2 * sn[t];
        qhi2[t] = x2 * cs[t] + x1 * sn[t];
        float y1 = k[base + d], y2 = k[base + d + 64];
        klo[t]  = y1 * cs[t] - y2 * sn[t];
        khi2[t] = y2 * cs[t] + y1 * sn[t];
    }
    #pragma unroll
    for (int t = 0; t < 2; t++) {
        q[base + 2 * jj + t]      = qlo[t];
        q[base + 2 * jj + t + 64] = qhi2[t];
    }
    int bh = b * NHEAD + h;
    size_t kbase = ((size_t)bh * SEQ + s) * 64;
    __nv_bfloat16 h0, l0, h1, l1;
    split_bf(klo[0], h0, l0); split_bf(klo[1], h1, l1);
    kph[kbase + jj] = pack_bf2(h0, h1);
    kpl[kbase + jj] = pack_bf2(l0, l1);
    split_bf(khi2[0], h0, l0); split_bf(khi2[1], h1, l1);
    kph[kbase + jj + 32] = pack_bf2(h0, h1);
    kpl[kbase + jj + 32] = pack_bf2(l0, l1);
}

__global__ void vpack(const float* __restrict__ v,
                      unsigned* __restrict__ vph, unsigned* __restrict__ vpl)
{
    int idx = blockIdx.x * blockDim.x + threadIdx.x;
    if (idx >= 32 * 1024 * 128) return;
    int nn = idx & 127;
    int kw = (idx >> 7) & 1023;
    int bh = idx >> 17;
    int b = bh >> 4, h = bh & 15;
    size_t addr = ((size_t)(b * SEQ + 2 * kw)) * EMB + h * DHEAD + nn;
    float v0 = v[addr], v1 = v[addr + EMB];
    __half h0, l0, h1, l1;
    split_h_plain(v0, h0, l0); split_h_plain(v1, h1, l1);
    vph[idx] = pack_h2(h0, h1);
    vpl[idx] = pack_h2(l0, l1);
}

// ---------------------------------------------------------------------------
// Flash attention (unchanged from R11/R13)
// ---------------------------------------------------------------------------
#define KPP 68
#define VPP 136
#define FA2_SMEM ((64 * KPP * 2 + 32 * VPP * 2) * 4)

__global__ __launch_bounds__(256) void flash_mma(
    const float* __restrict__ q,
    const unsigned* __restrict__ kph, const unsigned* __restrict__ kpl,
    const unsigned* __restrict__ vph, const unsigned* __restrict__ vpl,
    float* __restrict__ o)
{
    extern __shared__ unsigned sw_[];
    unsigned* Kph = sw_;
    unsigned* Kpl = Kph + 64 * KPP;
    unsigned* Vph = Kpl + 64 * KPP;
    unsigned* Vpl = Vph + 32 * VPP;

    const int tid = threadIdx.x;
    const int lane = tid & 31, wm = tid >> 5;
    const int l4 = lane >> 2, lk = lane & 3;
    const int iblk = (int)gridDim.x - 1 - (int)blockIdx.x;
    const int bh = blockIdx.y;
    const int b = bh >> 4, h = bh & 15;
    const size_t rowbase = (size_t)b * SEQ;
    const int m0 = iblk * 128;
    const float scale = 0.08838834764831845f;

    unsigned qh[8][4], ql[8][4];
    {
        const int r0 = m0 + wm * 16 + l4;
        #pragma unroll
        for (int s = 0; s < 8; s++) {
            #pragma unroll
            for (int f = 0; f < 4; f++) {
                int r = r0 + ((f & 1) ? 8 : 0);
                int d = 16 * s + 2 * lk + ((f & 2) ? 8 : 0);
                float2 qv = *(const float2*)(q + (rowbase + r) * EMB + h * DHEAD + d);
                float x = qv.x * scale, y = qv.y * scale;
                __nv_bfloat16 hx, lx, hy, ly;
                split_bf(x, hx, lx); split_bf(y, hy, ly);
                qh[s][f] = pack_bf2(hx, hy);
                ql[s][f] = pack_bf2(lx, ly);
            }
        }
    }

    float mr0 = -1e30f, mr1 = -1e30f, lr0 = 0.f, lr1 = 0.f;
    float oacc[16][4];
    #pragma unroll
    for (int nt = 0; nt < 16; nt++)
        #pragma unroll
        for (int i = 0; i < 4; i++) oacc[nt][i] = 0.f;

    const size_t kbase = (size_t)bh * SEQ * 64;
    const size_t vbase = (size_t)bh * 1024 * 128;

    const int ntiles = 2 * iblk + 2;
    for (int j = 0; j < ntiles; j++) {
        #pragma unroll
        for (int i = 0; i < 4; i++) {
            int lin = tid + 256 * i;
            int r = lin >> 4, c4 = (lin & 15) << 2;
            size_t src = kbase + (size_t)(j * 64 + r) * 64 + c4;
            *(uint4*)&Kph[r * KPP + c4] = *(const uint4*)(kph + src);
            *(uint4*)&Kpl[r * KPP + c4] = *(const uint4*)(kpl + src);
        }
        #pragma unroll
        for (int i = 0; i < 4; i++) {
            int lin = tid + 256 * i;
            int r = lin >> 5, c4 = (lin & 31) << 2;
            size_t src = vbase + (size_t)(j * 32 + r) * 128 + c4;
            *(uint4*)&Vph[r * VPP + c4] = *(const uint4*)(vph + src);
            *(uint4*)&Vpl[r * VPP + c4] = *(const uint4*)(vpl + src);
        }
        __syncthreads();

        float sacc[8][4];
        #pragma unroll
        for (int nt = 0; nt < 8; nt++)
            #pragma unroll
            for (int i = 0; i < 4; i++) sacc[nt][i] = 0.f;

        #pragma unroll
        for (int s = 0; s < 8; s++) {
            #pragma unroll
            for (int nt = 0; nt < 8; nt++) {
                int kr = (nt * 8 + l4) * KPP + 8 * s + lk;
                unsigned b_hi[2], b_lo[2];
                b_hi[0] = Kph[kr];
                b_hi[1] = Kph[kr + 4];
                b_lo[0] = Kpl[kr];
                b_lo[1] = Kpl[kr + 4];
                mma_bf16(sacc[nt], qh[s], b_hi);
                mma_bf16(sacc[nt], qh[s], b_lo);
                mma_bf16(sacc[nt], ql[s], b_hi);
            }
        }

        if (j >= 2 * iblk) {
            int row0 = m0 + wm * 16 + l4;
            #pragma unroll
            for (int nt = 0; nt < 8; nt++) {
                int col = j * 64 + nt * 8 + 2 * lk;
                if (col     > row0)     sacc[nt][0] = -1e30f;
                if (col + 1 > row0)     sacc[nt][1] = -1e30f;
                if (col     > row0 + 8) sacc[nt][2] = -1e30f;
                if (col + 1 > row0 + 8) sacc[nt][3] = -1e30f;
            }
        }

        float mx0 = -1e30f, mx1 = -1e30f;
        #pragma unroll
        for (int nt = 0; nt < 8; nt++) {
            mx0 = fmaxf(mx0, fmaxf(sacc[nt][0], sacc[nt][1]));
            mx1 = fmaxf(mx1, fmaxf(sacc[nt][2], sacc[nt][3]));
        }
        mx0 = fmaxf(mx0, __shfl_xor_sync(0xffffffffu, mx0, 1));
        mx0 = fmaxf(mx0, __shfl_xor_sync(0xffffffffu, mx0, 2));
        mx1 = fmaxf(mx1, __shfl_xor_sync(0xffffffffu, mx1, 1));
        mx1 = fmaxf(mx1, __shfl_xor_sync(0xffffffffu, mx1, 2));

        float mn0 = fmaxf(mr0, mx0), mn1 = fmaxf(mr1, mx1);
        float al0 = exp2q((mr0 - mn0) * L2E);
        float al1 = exp2q((mr1 - mn1) * L2E);
        mr0 = mn0; mr1 = mn1;
        float mnl0 = mn0 * L2E, mnl1 = mn1 * L2E;

        unsigned ph01[8], ph23[8];
        float rs0 = 0.f, rs1 = 0.f;
        #pragma unroll
        for (int nt = 0; nt < 8; nt++) {
            float p0 = exp2q(fmaf(sacc[nt][0], L2E, -mnl0));
            float p1 = exp2q(fmaf(sacc[nt][1], L2E, -mnl0));
            float p2 = exp2q(fmaf(sacc[nt][2], L2E, -mnl1));
            float p3 = exp2q(fmaf(sacc[nt][3], L2E, -mnl1));
            rs0 += p0 + p1; rs1 += p2 + p3;
            ph01[nt] = pack_h2(__float2half_rn(p0), __float2half_rn(p1));
            ph23[nt] = pack_h2(__float2half_rn(p2), __float2half_rn(p3));
        }
        rs0 += __shfl_xor_sync(0xffffffffu, rs0, 1);
        rs0 += __shfl_xor_sync(0xffffffffu, rs0, 2);
        rs1 += __shfl_xor_sync(0xffffffffu, rs1, 1);
        rs1 += __shfl_xor_sync(0xffffffffu, rs1, 2);
        lr0 = lr0 * al0 + rs0;
        lr1 = lr1 * al1 + rs1;

        #pragma unroll
        for (int nt = 0; nt < 16; nt++) {
            oacc[nt][0] *= al0; oacc[nt][1] *= al0;
            oacc[nt][2] *= al1; oacc[nt][3] *= al1;
        }

        #pragma unroll
        for (int t = 0; t < 4; t++) {
            unsigned pa[4];
            pa[0] = ph01[2 * t];
            pa[1] = ph23[2 * t];
            pa[2] = ph01[2 * t + 1];
            pa[3] = ph23[2 * t + 1];
            #pragma unroll
            for (int nt = 0; nt < 16; nt++) {
                int vr = (8 * t + lk) * VPP + nt * 8 + l4;
                unsigned b_hi[2], b_lo[2];
                b_hi[0] = Vph[vr];
                b_hi[1] = Vph[vr + 4 * VPP];
                b_lo[0] = Vpl[vr];
                b_lo[1] = Vpl[vr + 4 * VPP];
                mma_f16_f32(oacc[nt], pa, b_hi);
                mma_f16_f32(oacc[nt], pa, b_lo);
            }
        }
        __syncthreads();
    }

    float il0 = 1.f / lr0, il1 = 1.f / lr1;
    int row0 = m0 + wm * 16 + l4;
    #pragma unroll
    for (int nt = 0; nt < 16; nt++) {
        int col = h * DHEAD + nt * 8 + 2 * lk;
        float2 o0 = make_float2(oacc[nt][0] * il0, oacc[nt][1] * il0);
        float2 o1 = make_float2(oacc[nt][2] * il1, oacc[nt][3] * il1);
        *(float2*)(o + (rowbase + row0) * EMB + col)     = o0;
        *(float2*)(o + (rowbase + row0 + 8) * EMB + col) = o1;
    }
}

// ---------------------------------------------------------------------------
extern "C" void kernel_launch(void* const* d_in, const int* in_sizes, int n_in,
                              void* d_out, int out_size)
{
    const float* x    = (const float*)d_in[0];
    const float* mask = (const float*)d_in[1];
    const float* Wq = (const float*)d_in[2];  const float* bq = (const float*)d_in[3];
    const float* Aq = (const float*)d_in[4];  const float* Bq = (const float*)d_in[5];
    const float* Cq = (const float*)d_in[6];  const float* Rq = (const float*)d_in[7];
    const float* Wk = (const float*)d_in[8];  const float* bk = (const float*)d_in[9];
    const float* Ak = (const float*)d_in[10]; const float* Bk = (const float*)d_in[11];
    const float* Ck = (const float*)d_in[12]; const float* Rk = (const float*)d_in[13];
    const float* Wv = (const float*)d_in[14]; const float* bv = (const float*)d_in[15];
    const float* Av = (const float*)d_in[16]; const float* Bv = (const float*)d_in[17];
    const float* Cv = (const float*)d_in[18]; const float* Rv = (const float*)d_in[19];
    const float* Wo = (const float*)d_in[20]; const float* Ao = (const float*)d_in[21];
    const float* Bo = (const float*)d_in[22]; const float* Co = (const float*)d_in[23];
    const float* Ro = (const float*)d_in[24];

    float *q, *k, *v, *att;
    __half *xh, *xl, *hh, *hl, *w16;
    unsigned *kph, *kpl, *vph, *vpl;
    cudaGetSymbolAddress((void**)&q,   g_q);
    cudaGetSymbolAddress((void**)&k,   g_k);
    cudaGetSymbolAddress((void**)&v,   g_v);
    cudaGetSymbolAddress((void**)&att, g_att);
    cudaGetSymbolAddress((void**)&xh,  g_xh);
    cudaGetSymbolAddress((void**)&xl,  g_xl);
    cudaGetSymbolAddress((void**)&hh,  g_hh);
    cudaGetSymbolAddress((void**)&hl,  g_hl);
    cudaGetSymbolAddress((void**)&w16, g_w16);
    cudaGetSymbolAddress((void**)&kph, g_kph);
    cudaGetSymbolAddress((void**)&kpl, g_kpl);
    cudaGetSymbolAddress((void**)&vph, g_vph);
    cudaGetSymbolAddress((void**)&vpl, g_vpl);

    cudaFuncSetAttribute(flash_mma,
                         cudaFuncAttributeMaxDynamicSharedMemorySize, FA2_SMEM);
    cudaFuncSetAttribute(gemm_ps,
                         cudaFuncAttributeMaxDynamicSharedMemorySize, GPS_SMEM);

    const size_t HSTR = (size_t)ROWS * 96;
    const size_t WSTR = (size_t)2048 * KAUG;
    dim3 ggrid(EMB / 128, ROWS / 128);   // (16, 32)

    // one-time packs
    pack_w16<<<dim3(2048, 4), 256>>>(Wq, Bq, Rq, Wk, Bk, Rk, Wv, Bv, Rv, Wo, Bo, Ro, w16);
    aux_mma<<<dim3(3, ROWS / 128), 256>>>(x, mask, Aq, Cq, Ak, Ck, Av, Cv,
                                          hh, hl, hh + HSTR, hl + HSTR,
                                          hh + 2 * HSTR, hl + 2 * HSTR);
    pack_x<<<(ROWS * EMB / 8) / 256, 256>>>(x, xh, xl);
    // projections
    gemm_ps<<<ggrid, 256, GPS_SMEM>>>(xh, xl, hh, hl, w16, bq, q);
    gemm_ps<<<ggrid, 256, GPS_SMEM>>>(xh, xl, hh + HSTR, hl + HSTR, w16 + WSTR, bk, k);
    gemm_ps<<<ggrid, 256, GPS_SMEM>>>(xh, xl, hh + 2 * HSTR, hl + 2 * HSTR,
                                      w16 + 2 * WSTR, bv, v);
    // rope + flash packs
    rope_pack<<<(ROWS * NHEAD * 32 + 255) / 256, 256>>>(q, k, kph, kpl);
    vpack<<<(32 * 1024 * 128 + 255) / 256, 256>>>(v, vph, vpl);
    // flash attention
    flash_mma<<<dim3(SEQ / 128, BATCH * NHEAD), 256, FA2_SMEM>>>(q, kph, kpl, vph, vpl, att);
    // output projection
    aux_mma<<<dim3(1, ROWS / 128), 256>>>(att, mask, Ao, Co, Ao, Co, Ao, Co,
                                          hh + 3 * HSTR, hl + 3 * HSTR,
                                          hh + 3 * HSTR, hl + 3 * HSTR,
                                          hh + 3 * HSTR, hl + 3 * HSTR);
    pack_x<<<(ROWS * EMB / 8) / 256, 256>>>(att, xh, xl);
    gemm_ps<<<ggrid, 256, GPS_SMEM>>>(xh, xl, hh + 3 * HSTR, hl + 3 * HSTR,
                                      w16 + 3 * WSTR, nullptr, (float*)d_out);
}

// round 15
// speedup vs baseline: 1.3646x; 1.0896x over previous
#include <cuda_runtime.h>
#include <cuda_bf16.h>
#include <cuda_fp16.h>
#include <cstdint>
#include <math.h>

#define BATCH 2
#define SEQ   2048
#define EMB   2048
#define NHEAD 16
#define DHEAD 128
#define NEXP_ 64
#define RLORA 32
#define ROWS  4096
#define KAUG  2144
#define NCH2  67          // K chunks of 32

// ---------------- scratch ----------------
__device__ float g_q[(size_t)ROWS * EMB];
__device__ float g_k[(size_t)ROWS * EMB];
__device__ float g_v[(size_t)ROWS * EMB];
__device__ __half g_xh[(size_t)ROWS * EMB];
__device__ __half g_xl[(size_t)ROWS * EMB];
__device__ __half g_hh[4][(size_t)ROWS * 96];
__device__ __half g_hl[4][(size_t)ROWS * 96];
__device__ __half g_w16[(size_t)4 * 2048 * KAUG];
__device__ unsigned g_kph[(size_t)32 * 2048 * 64];
__device__ unsigned g_kpl[(size_t)32 * 2048 * 64];
__device__ unsigned g_vph[(size_t)32 * 1024 * 128];
__device__ unsigned g_vpl[(size_t)32 * 1024 * 128];

// ---------------- helpers ----------------
__device__ __forceinline__ unsigned pack_bf2(__nv_bfloat16 a, __nv_bfloat16 b) {
    return (unsigned)__bfloat16_as_ushort(a) | ((unsigned)__bfloat16_as_ushort(b) << 16);
}
__device__ __forceinline__ void split_bf(float x, __nv_bfloat16& hi, __nv_bfloat16& lo) {
    hi = __float2bfloat16_rn(x);
    lo = __float2bfloat16_rn(x - __bfloat162float(hi));
}
__device__ __forceinline__ unsigned pack_h2(__half a, __half b) {
    __half2 t = __halves2half2(a, b);
    return *(unsigned*)&t;
}
__device__ __forceinline__ void split_h_plain(float x, __half& hi, __half& lo) {
    hi = __float2half_rn(x);
    lo = __float2half_rn(x - __half2float(hi));
}
__device__ __forceinline__ void mma_bf16(float* c, const unsigned* a, const unsigned* b) {
    asm volatile(
        "mma.sync.aligned.m16n8k16.row.col.f32.bf16.bf16.f32 "
        "{%0,%1,%2,%3}, {%4,%5,%6,%7}, {%8,%9}, {%0,%1,%2,%3};"
        : "+f"(c[0]), "+f"(c[1]), "+f"(c[2]), "+f"(c[3])
        : "r"(a[0]), "r"(a[1]), "r"(a[2]), "r"(a[3]), "r"(b[0]), "r"(b[1]));
}
__device__ __forceinline__ void mma_f16_f32(float* c, const unsigned* a, const unsigned* b) {
    asm volatile(
        "mma.sync.aligned.m16n8k16.row.col.f32.f16.f16.f32 "
        "{%0,%1,%2,%3}, {%4,%5,%6,%7}, {%8,%9}, {%0,%1,%2,%3};"
        : "+f"(c[0]), "+f"(c[1]), "+f"(c[2]), "+f"(c[3])
        : "r"(a[0]), "r"(a[1]), "r"(a[2]), "r"(a[3]), "r"(b[0]), "r"(b[1]));
}
__device__ __forceinline__ void cp16(unsigned saddr, const void* g) {
    asm volatile("cp.async.cg.shared.global [%0], [%1], 16;" :: "r"(saddr), "l"(g) : "memory");
}
#define CP_COMMIT asm volatile("cp.async.commit_group;\n" ::: "memory")
__device__ __forceinline__ unsigned s2u(const void* p) {
    unsigned a;
    asm("{ .reg .u64 t; cvta.to.shared.u64 t, %1; cvt.u32.u64 %0, t; }" : "=r"(a) : "l"(p));
    return a;
}

#define L2E 1.4426950408889634f
__device__ __forceinline__ float exp2q(float t) {
    t = fmaxf(t, -126.f);
    float z = t + 12582912.f;
    int ni = __float_as_int(z) - 0x4B400000;
    float r = t - (z - 12582912.f);
    float p = 1.3333558146e-3f;
    p = fmaf(p, r, 9.6181291876e-3f);
    p = fmaf(p, r, 5.5504108665e-2f);
    p = fmaf(p, r, 2.4022650696e-1f);
    p = fmaf(p, r, 6.9314718056e-1f);
    p = fmaf(p, r, 1.0f);
    return p * __int_as_float((ni + 127) << 23);
}

// ---------------------------------------------------------------------------
// pack_x: fp32 -> fp16 hi/lo planes
// ---------------------------------------------------------------------------
__global__ void pack_x(const float* __restrict__ src,
                       __half* __restrict__ dh, __half* __restrict__ dl)
{
    size_t i = ((size_t)blockIdx.x * 256 + threadIdx.x) * 8;
    float4 v0 = *(const float4*)(src + i);
    float4 v1 = *(const float4*)(src + i + 4);
    __half h[8], l[8];
    split_h_plain(v0.x, h[0], l[0]); split_h_plain(v0.y, h[1], l[1]);
    split_h_plain(v0.z, h[2], l[2]); split_h_plain(v0.w, h[3], l[3]);
    split_h_plain(v1.x, h[4], l[4]); split_h_plain(v1.y, h[5], l[5]);
    split_h_plain(v1.z, h[6], l[6]); split_h_plain(v1.w, h[7], l[7]);
    uint4 ph = make_uint4(pack_h2(h[0], h[1]), pack_h2(h[2], h[3]),
                          pack_h2(h[4], h[5]), pack_h2(h[6], h[7]));
    uint4 pl = make_uint4(pack_h2(l[0], l[1]), pack_h2(l[2], l[3]),
                          pack_h2(l[4], l[5]), pack_h2(l[6], l[7]));
    *(uint4*)(dh + i) = ph;
    *(uint4*)(dl + i) = pl;
}

// ---------------------------------------------------------------------------
// pack_w16: concat [W | Bl | Rr] rows -> fp16, KAUG stride, 4 projections
// ---------------------------------------------------------------------------
__global__ void pack_w16(
    const float* __restrict__ W0, const float* __restrict__ B0, const float* __restrict__ R0,
    const float* __restrict__ W1, const float* __restrict__ B1, const float* __restrict__ R1,
    const float* __restrict__ W2, const float* __restrict__ B2, const float* __restrict__ R2,
    const float* __restrict__ W3, const float* __restrict__ B3, const float* __restrict__ R3,
    __half* __restrict__ w16)
{
    const int n = blockIdx.x, p = blockIdx.y;
    const float* W = (p == 0) ? W0 : (p == 1) ? W1 : (p == 2) ? W2 : W3;
    const float* Bm = (p == 0) ? B0 : (p == 1) ? B1 : (p == 2) ? B2 : B3;
    const float* Rm = (p == 0) ? R0 : (p == 1) ? R1 : (p == 2) ? R2 : R3;
    __half* d = w16 + ((size_t)p * 2048 + n) * KAUG;

    for (int k = threadIdx.x * 4; k < KAUG; k += 1024) {
        float4 v;
        if (k < EMB)              v = *(const float4*)(W + (size_t)n * EMB + k);
        else if (k < EMB + RLORA) v = *(const float4*)(Bm + (size_t)n * RLORA + (k - EMB));
        else                      v = *(const float4*)(Rm + (size_t)n * NEXP_ + (k - EMB - RLORA));
        uint2 o = make_uint2(pack_h2(__float2half_rn(v.x), __float2half_rn(v.y)),
                             pack_h2(__float2half_rn(v.z), __float2half_rn(v.w)));
        *(uint2*)(d + k) = o;
    }
}

// ---------------------------------------------------------------------------
// aux GEMM, fp16 2-term: A from presplit xh/xl planes (no conversion),
// B truncated fp16 in-kernel. Tile 128x96x32, 8 warps (4m x 2n), warp 32x48.
// Outputs fp16 hi/lo haux planes with silu + expert mask.
// ---------------------------------------------------------------------------
__global__ __launch_bounds__(256) void aux_mma(
    const __half* __restrict__ xh, const __half* __restrict__ xl,
    const float* __restrict__ mask,
    const float* __restrict__ A0, const float* __restrict__ C0,
    const float* __restrict__ A1, const float* __restrict__ C1,
    const float* __restrict__ A2, const float* __restrict__ C2,
    __half* __restrict__ hh0, __half* __restrict__ hl0,
    __half* __restrict__ hh1, __half* __restrict__ hl1,
    __half* __restrict__ hh2, __half* __restrict__ hl2)
{
    __shared__ unsigned Ah[128][20], Al[128][20];
    __shared__ unsigned Bh[96][20];

    const int proj = blockIdx.x;
    const int m0 = blockIdx.y * 128;
    const float* A = (proj == 0) ? A0 : ((proj == 1) ? A1 : A2);
    const float* C = (proj == 0) ? C0 : ((proj == 1) ? C1 : C2);
    __half* hh = (proj == 0) ? hh0 : ((proj == 1) ? hh1 : hh2);
    __half* hl = (proj == 0) ? hl0 : ((proj == 1) ? hl1 : hl2);

    const int tid = threadIdx.x;
    const int lane = tid & 31, wid = tid >> 5;
    const int l4 = lane >> 2, lk = lane & 3;
    const int warp_m = wid & 3, warp_n = wid >> 2;

    float c[2][6][4];
    #pragma unroll
    for (int mt = 0; mt < 2; mt++)
        #pragma unroll
        for (int nt = 0; nt < 6; nt++)
            #pragma unroll
            for (int i = 0; i < 4; i++) c[mt][nt][i] = 0.f;

    for (int k0 = 0; k0 < EMB; k0 += 32) {
        // A: copy fp16 planes straight into smem (1024 uint4 total)
        #pragma unroll
        for (int i = 0; i < 4; i++) {
            int lin = tid + 256 * i;               // 1024 slots
            int r = lin >> 3, half8 = lin & 7;     // 8 x uint4 per row (2 planes x 4)
            int pl = half8 >> 2, q = half8 & 3;    // plane, quarter
            const __half* src = (pl == 0) ? xh : xl;
            uint4 vv = *(const uint4*)(src + (size_t)(m0 + r) * EMB + k0 + q * 8);
            unsigned* dst = (pl == 0) ? &Ah[r][q * 4] : &Al[r][q * 4];
            *(uint4*)dst = vv;
        }
        // B: 96 rows x 32 k, truncate fp32 -> fp16 (768 float4 slots)
        #pragma unroll
        for (int i = 0; i < 3; i++) {
            int lin = tid + 256 * i;
            if (lin < 768) {
                int r = lin >> 3, c4 = (lin & 7) << 2;
                const float* src = (r < 32) ? (A + (size_t)r * EMB)
                                            : (C + (size_t)(r - 32) * EMB);
                float4 vb = *(const float4*)(src + k0 + c4);
                *(uint2*)&Bh[r][c4 >> 1] = make_uint2(
                    pack_h2(__float2half_rn(vb.x), __float2half_rn(vb.y)),
                    pack_h2(__float2half_rn(vb.z), __float2half_rn(vb.w)));
            }
        }
        __syncthreads();

        #pragma unroll
        for (int ks = 0; ks < 2; ks++) {
            const int kw = ks * 8;
            unsigned ah[2][4], al[2][4];
            #pragma unroll
            for (int mt = 0; mt < 2; mt++) {
                int rb = warp_m * 32 + mt * 16 + l4;
                ah[mt][0] = Ah[rb][kw + lk];
                ah[mt][1] = Ah[rb + 8][kw + lk];
                ah[mt][2] = Ah[rb][kw + 4 + lk];
                ah[mt][3] = Ah[rb + 8][kw + 4 + lk];
                al[mt][0] = Al[rb][kw + lk];
                al[mt][1] = Al[rb + 8][kw + lk];
                al[mt][2] = Al[rb][kw + 4 + lk];
                al[mt][3] = Al[rb + 8][kw + 4 + lk];
            }
            #pragma unroll
            for (int nt = 0; nt < 6; nt++) {
                int cb = warp_n * 48 + nt * 8 + l4;
                unsigned bh[2];
                bh[0] = Bh[cb][kw + lk];
                bh[1] = Bh[cb][kw + 4 + lk];
                #pragma unroll
                for (int mt = 0; mt < 2; mt++) {
                    mma_f16_f32(c[mt][nt], ah[mt], bh);
                    mma_f16_f32(c[mt][nt], al[mt], bh);
                }
            }
        }
        __syncthreads();
    }

    #pragma unroll
    for (int mt = 0; mt < 2; mt++) {
        int r0 = m0 + warp_m * 32 + mt * 16 + l4;
        #pragma unroll
        for (int nt = 0; nt < 6; nt++) {
            int u = warp_n * 48 + nt * 8 + 2 * lk;
            #pragma unroll
            for (int half = 0; half < 2; half++) {
                int row = r0 + half * 8;
                float v0 = c[mt][nt][half * 2 + 0];
                float v1 = c[mt][nt][half * 2 + 1];
                float s0 = v0 / (1.f + __expf(-v0));
                float s1 = v1 / (1.f + __expf(-v1));
                if (u >= 32)     s0 *= mask[(size_t)row * NEXP_ + (u - 32)];
                if (u + 1 >= 32) s1 *= mask[(size_t)row * NEXP_ + (u + 1 - 32)];
                __half h0, l0, h1, l1;
                split_h_plain(s0, h0, l0);
                split_h_plain(s1, h1, l1);
                hh[(size_t)row * 96 + u]     = h0;
                hh[(size_t)row * 96 + u + 1] = h1;
                hl[(size_t)row * 96 + u]     = l0;
                hl[(size_t)row * 96 + u + 1] = l1;
            }
        }
    }
}

// ---------------------------------------------------------------------------
// Presplit fp16 2-term GEMM, 3-stage cp.async pipeline, multi-projection:
// proj = blockIdx.x >> 4, n0 = (blockIdx.x & 15)*128.
// ---------------------------------------------------------------------------
#define PLW   (128 * 20)
#define STGW  (3 * PLW)
#define GPS_SMEM (3 * STGW * 4)

__global__ __launch_bounds__(256, 2) void gemm_ps3(
    const __half* __restrict__ xh, const __half* __restrict__ xl,
    const __half* __restrict__ hhb, const __half* __restrict__ hlb, size_t hstr,
    const __half* __restrict__ w16b, size_t wstr,
    const float* __restrict__ b0, const float* __restrict__ b1,
    const float* __restrict__ b2,
    float* __restrict__ o0, float* __restrict__ o1, float* __restrict__ o2)
{
    extern __shared__ unsigned smw[];
    const unsigned dsm = s2u(smw);
    const int tid = threadIdx.x;
    const int lane = tid & 31, wid = tid >> 5;
    const int l4 = lane >> 2, lk = lane & 3;
    const int warp_m = wid & 3, warp_n = wid >> 2;
    const int p = blockIdx.x >> 4;
    const int m0 = blockIdx.y * 128, n0 = (blockIdx.x & 15) * 128;
    const __half* hh  = hhb + (size_t)p * hstr;
    const __half* hl  = hlb + (size_t)p * hstr;
    const __half* w16 = w16b + (size_t)p * wstr;
    const float* bias = (p == 0) ? b0 : (p == 1) ? b1 : b2;
    float* out        = (p == 0) ? o0 : (p == 1) ? o1 : o2;

    float c[2][8][4];
    #pragma unroll
    for (int mt = 0; mt < 2; mt++)
        #pragma unroll
        for (int nt = 0; nt < 8; nt++)
            #pragma unroll
            for (int i = 0; i < 4; i++) c[mt][nt][i] = 0.f;

    const int r0f = tid >> 2, q0f = tid & 3;

#define FILLP(STG, CC) do {                                                     \
    int c_ = (CC);                                                              \
    unsigned sb_ = dsm + (STG) * STGW * 4;                                      \
    const __half *pah_, *pal_; int str_;                                        \
    if (c_ < 64) { pah_ = xh + (size_t)m0 * EMB + c_ * 32;                      \
                   pal_ = xl + (size_t)m0 * EMB + c_ * 32; str_ = EMB; }        \
    else         { pah_ = hh + (size_t)m0 * 96 + (c_ - 64) * 32;                \
                   pal_ = hl + (size_t)m0 * 96 + (c_ - 64) * 32; str_ = 96; }   \
    const __half* pw_ = w16 + (size_t)n0 * KAUG + c_ * 32;                      \
    cp16(sb_ + (r0f * 20 + q0f * 4) * 4,        pah_ + (size_t)r0f * str_ + q0f * 8); \
    cp16(sb_ + ((r0f + 64) * 20 + q0f * 4) * 4, pah_ + (size_t)(r0f + 64) * str_ + q0f * 8); \
    cp16(sb_ + (PLW + r0f * 20 + q0f * 4) * 4,        pal_ + (size_t)r0f * str_ + q0f * 8); \
    cp16(sb_ + (PLW + (r0f + 64) * 20 + q0f * 4) * 4, pal_ + (size_t)(r0f + 64) * str_ + q0f * 8); \
    cp16(sb_ + (2 * PLW + r0f * 20 + q0f * 4) * 4,        pw_ + (size_t)r0f * KAUG + q0f * 8); \
    cp16(sb_ + (2 * PLW + (r0f + 64) * 20 + q0f * 4) * 4, pw_ + (size_t)(r0f + 64) * KAUG + q0f * 8); \
} while (0)

    FILLP(0, 0); CP_COMMIT;
    FILLP(1, 1); CP_COMMIT;

    for (int cc = 0; cc < NCH2; cc++) {
        asm volatile("cp.async.wait_group 1;" ::: "memory");
        __syncthreads();

        int nf = cc + 2;
        if (nf < NCH2) FILLP(nf % 3, nf);
        CP_COMMIT;

        const unsigned* Ahp = smw + (cc % 3) * STGW;
        const unsigned* Alp = Ahp + PLW;
        const unsigned* Wp  = Ahp + 2 * PLW;

        #pragma unroll
        for (int ks = 0; ks < 2; ks++) {
            const int kw = ks * 8;
            unsigned a_hi[2][4], a_lo[2][4];
            #pragma unroll
            for (int mt = 0; mt < 2; mt++) {
                int rb = warp_m * 32 + mt * 16 + l4;
                a_hi[mt][0] = Ahp[rb * 20 + kw + lk];
                a_hi[mt][1] = Ahp[(rb + 8) * 20 + kw + lk];
                a_hi[mt][2] = Ahp[rb * 20 + kw + 4 + lk];
                a_hi[mt][3] = Ahp[(rb + 8) * 20 + kw + 4 + lk];
                a_lo[mt][0] = Alp[rb * 20 + kw + lk];
                a_lo[mt][1] = Alp[(rb + 8) * 20 + kw + lk];
                a_lo[mt][2] = Alp[rb * 20 + kw + 4 + lk];
                a_lo[mt][3] = Alp[(rb + 8) * 20 + kw + 4 + lk];
            }
            #pragma unroll
            for (int nt = 0; nt < 8; nt++) {
                int cb = warp_n * 64 + nt * 8 + l4;
                unsigned bh[2];
                bh[0] = Wp[cb * 20 + kw + lk];
                bh[1] = Wp[cb * 20 + kw + 4 + lk];
                #pragma unroll
                for (int mt = 0; mt < 2; mt++) {
                    mma_f16_f32(c[mt][nt], a_hi[mt], bh);
                    mma_f16_f32(c[mt][nt], a_lo[mt], bh);
                }
            }
        }
    }
#undef FILLP

    float2 bv[8];
    #pragma unroll
    for (int nt = 0; nt < 8; nt++) {
        int col = n0 + warp_n * 64 + nt * 8 + 2 * lk;
        if (bias) bv[nt] = *(const float2*)(bias + col);
        else      bv[nt] = make_float2(0.f, 0.f);
    }
    #pragma unroll
    for (int mt = 0; mt < 2; mt++) {
        int r0 = m0 + warp_m * 32 + mt * 16 + l4;
        #pragma unroll
        for (int nt = 0; nt < 8; nt++) {
            int col = n0 + warp_n * 64 + nt * 8 + 2 * lk;
            float2 q0 = make_float2(c[mt][nt][0] + bv[nt].x, c[mt][nt][1] + bv[nt].y);
            float2 q1 = make_float2(c[mt][nt][2] + bv[nt].x, c[mt][nt][3] + bv[nt].y);
            *(float2*)(out + (size_t)r0 * EMB + col)       = q0;
            *(float2*)(out + (size_t)(r0 + 8) * EMB + col) = q1;
        }
    }
}

// ---------------------------------------------------------------------------
// rope_pack / vpack (unchanged)
// ---------------------------------------------------------------------------
__global__ void rope_pack(float* __restrict__ q, const float* __restrict__ k,
                          unsigned* __restrict__ kph, unsigned* __restrict__ kpl)
{
    int idx = blockIdx.x * blockDim.x + threadIdx.x;
    if (idx >= ROWS * NHEAD * 32) return;
    int jj  = idx & 31;
    int h   = (idx >> 5) & 15;
    int row = idx >> 9;
    int s   = row & (SEQ - 1);
    int b   = row >> 11;

    float sn[2], cs[2];
    #pragma unroll
    for (int t = 0; t < 2; t++) {
        int d = 2 * jj + t;
        float e = (float)(2 * d) * (1.0f / 128.0f);
        float inv = powf(10000.0f, -e);
        sincosf((float)s * inv, &sn[t], &cs[t]);
    }

    size_t base = (size_t)row * EMB + h * DHEAD;
    float qlo[2], qhi2[2], klo[2], khi2[2];
    #pragma unroll
    for (int t = 0; t < 2; t++) {
        int d = 2 * jj + t;
        float x1 = q[base + d], x2 = q[base + d + 64];
        qlo[t]  = x1 * cs[t] - x2 * sn[t];
        qhi2[t] = x2 * cs[t] + x1 * sn[t];
        float y1 = k[base + d], y2 = k[base + d + 64];
        klo[t]  = y1 * cs[t] - y2 * sn[t];
        khi2[t] = y2 * cs[t] + y1 * sn[t];
    }
    #pragma unroll
    for (int t = 0; t < 2; t++) {
        q[base + 2 * jj + t]      = qlo[t];
        q[base + 2 * jj + t + 64] = qhi2[t];
    }
    int bh = b * NHEAD + h;
    size_t kbase = ((size_t)bh * SEQ + s) * 64;
    __nv_bfloat16 h0, l0, h1, l1;
    split_bf(klo[0], h0, l0); split_bf(klo[1], h1, l1);
    kph[kbase + jj] = pack_bf2(h0, h1);
    kpl[kbase + jj] = pack_bf2(l0, l1);
    split_bf(khi2[0], h0, l0); split_bf(khi2[1], h1, l1);
    kph[kbase + jj + 32] = pack_bf2(h0, h1);
    kpl[kbase + jj + 32] = pack_bf2(l0, l1);
}

__global__ void vpack(const float* __restrict__ v,
                      unsigned* __restrict__ vph, unsigned* __restrict__ vpl)
{
    int idx = blockIdx.x * blockDim.x + threadIdx.x;
    if (idx >= 32 * 1024 * 128) return;
    int nn = idx & 127;
    int kw = (idx >> 7) & 1023;
    int bh = idx >> 17;
    int b = bh >> 4, h = bh & 15;
    size_t addr = ((size_t)(b * SEQ + 2 * kw)) * EMB + h * DHEAD + nn;
    float v0 = v[addr], v1 = v[addr + EMB];
    __half h0, l0, h1, l1;
    split_h_plain(v0, h0, l0); split_h_plain(v1, h1, l1);
    vph[idx] = pack_h2(h0, h1);
    vpl[idx] = pack_h2(l0, l1);
}

// ---------------------------------------------------------------------------
// Flash attention; epilogue writes fp16 hi/lo planes directly (no fp32 att).
// ---------------------------------------------------------------------------
#define KPP 68
#define VPP 136
#define FA2_SMEM ((64 * KPP * 2 + 32 * VPP * 2) * 4)

__global__ __launch_bounds__(256) void flash_mma(
    const float* __restrict__ q,
    const unsigned* __restrict__ kph, const unsigned* __restrict__ kpl,
    const unsigned* __restrict__ vph, const unsigned* __restrict__ vpl,
    __half* __restrict__ oh, __half* __restrict__ ol)
{
    extern __shared__ unsigned sw_[];
    unsigned* Kph = sw_;
    unsigned* Kpl = Kph + 64 * KPP;
    unsigned* Vph = Kpl + 64 * KPP;
    unsigned* Vpl = Vph + 32 * VPP;

    const int tid = threadIdx.x;
    const int lane = tid & 31, wm = tid >> 5;
    const int l4 = lane >> 2, lk = lane & 3;
    const int iblk = (int)gridDim.x - 1 - (int)blockIdx.x;
    const int bh = blockIdx.y;
    const int b = bh >> 4, h = bh & 15;
    const size_t rowbase = (size_t)b * SEQ;
    const int m0 = iblk * 128;
    const float scale = 0.08838834764831845f;

    unsigned qh[8][4], ql[8][4];
    {
        const int r0 = m0 + wm * 16 + l4;
        #pragma unroll
        for (int s = 0; s < 8; s++) {
            #pragma unroll
            for (int f = 0; f < 4; f++) {
                int r = r0 + ((f & 1) ? 8 : 0);
                int d = 16 * s + 2 * lk + ((f & 2) ? 8 : 0);
                float2 qv = *(const float2*)(q + (rowbase + r) * EMB + h * DHEAD + d);
                float x = qv.x * scale, y = qv.y * scale;
                __nv_bfloat16 hx, lx, hy, ly;
                split_bf(x, hx, lx); split_bf(y, hy, ly);
                qh[s][f] = pack_bf2(hx, hy);
                ql[s][f] = pack_bf2(lx, ly);
            }
        }
    }

    float mr0 = -1e30f, mr1 = -1e30f, lr0 = 0.f, lr1 = 0.f;
    float oacc[16][4];
    #pragma unroll
    for (int nt = 0; nt < 16; nt++)
        #pragma unroll
        for (int i = 0; i < 4; i++) oacc[nt][i] = 0.f;

    const size_t kbase = (size_t)bh * SEQ * 64;
    const size_t vbase = (size_t)bh * 1024 * 128;

    const int ntiles = 2 * iblk + 2;
    for (int j = 0; j < ntiles; j++) {
        #pragma unroll
        for (int i = 0; i < 4; i++) {
            int lin = tid + 256 * i;
            int r = lin >> 4, c4 = (lin & 15) << 2;
            size_t src = kbase + (size_t)(j * 64 + r) * 64 + c4;
            *(uint4*)&Kph[r * KPP + c4] = *(const uint4*)(kph + src);
            *(uint4*)&Kpl[r * KPP + c4] = *(const uint4*)(kpl + src);
        }
        #pragma unroll
        for (int i = 0; i < 4; i++) {
            int lin = tid + 256 * i;
            int r = lin >> 5, c4 = (lin & 31) << 2;
            size_t src = vbase + (size_t)(j * 32 + r) * 128 + c4;
            *(uint4*)&Vph[r * VPP + c4] = *(const uint4*)(vph + src);
            *(uint4*)&Vpl[r * VPP + c4] = *(const uint4*)(vpl + src);
        }
        __syncthreads();

        float sacc[8][4];
        #pragma unroll
        for (int nt = 0; nt < 8; nt++)
            #pragma unroll
            for (int i = 0; i < 4; i++) sacc[nt][i] = 0.f;

        #pragma unroll
        for (int s = 0; s < 8; s++) {
            #pragma unroll
            for (int nt = 0; nt < 8; nt++) {
                int kr = (nt * 8 + l4) * KPP + 8 * s + lk;
                unsigned b_hi[2], b_lo[2];
                b_hi[0] = Kph[kr];
                b_hi[1] = Kph[kr + 4];
                b_lo[0] = Kpl[kr];
                b_lo[1] = Kpl[kr + 4];
                mma_bf16(sacc[nt], qh[s], b_hi);
                mma_bf16(sacc[nt], qh[s], b_lo);
                mma_bf16(sacc[nt], ql[s], b_hi);
            }
        }

        if (j >= 2 * iblk) {
            int row0 = m0 + wm * 16 + l4;
            #pragma unroll
            for (int nt = 0; nt < 8; nt++) {
                int col = j * 64 + nt * 8 + 2 * lk;
                if (col     > row0)     sacc[nt][0] = -1e30f;
                if (col + 1 > row0)     sacc[nt][1] = -1e30f;
                if (col     > row0 + 8) sacc[nt][2] = -1e30f;
                if (col + 1 > row0 + 8) sacc[nt][3] = -1e30f;
            }
        }

        float mx0 = -1e30f, mx1 = -1e30f;
        #pragma unroll
        for (int nt = 0; nt < 8; nt++) {
            mx0 = fmaxf(mx0, fmaxf(sacc[nt][0], sacc[nt][1]));
            mx1 = fmaxf(mx1, fmaxf(sacc[nt][2], sacc[nt][3]));
        }
        mx0 = fmaxf(mx0, __shfl_xor_sync(0xffffffffu, mx0, 1));
        mx0 = fmaxf(mx0, __shfl_xor_sync(0xffffffffu, mx0, 2));
        mx1 = fmaxf(mx1, __shfl_xor_sync(0xffffffffu, mx1, 1));
        mx1 = fmaxf(mx1, __shfl_xor_sync(0xffffffffu, mx1, 2));

        float mn0 = fmaxf(mr0, mx0), mn1 = fmaxf(mr1, mx1);
        float al0 = exp2q((mr0 - mn0) * L2E);
        float al1 = exp2q((mr1 - mn1) * L2E);
        mr0 = mn0; mr1 = mn1;
        float mnl0 = mn0 * L2E, mnl1 = mn1 * L2E;

        unsigned ph01[8], ph23[8];
        float rs0 = 0.f, rs1 = 0.f;
        #pragma unroll
        for (int nt = 0; nt < 8; nt++) {
            float p0 = exp2q(fmaf(sacc[nt][0], L2E, -mnl0));
            float p1 = exp2q(fmaf(sacc[nt][1], L2E, -mnl0));
            float p2 = exp2q(fmaf(sacc[nt][2], L2E, -mnl1));
            float p3 = exp2q(fmaf(sacc[nt][3], L2E, -mnl1));
            rs0 += p0 + p1; rs1 += p2 + p3;
            ph01[nt] = pack_h2(__float2half_rn(p0), __float2half_rn(p1));
            ph23[nt] = pack_h2(__float2half_rn(p2), __float2half_rn(p3));
        }
        rs0 += __shfl_xor_sync(0xffffffffu, rs0, 1);
        rs0 += __shfl_xor_sync(0xffffffffu, rs0, 2);
        rs1 += __shfl_xor_sync(0xffffffffu, rs1, 1);
        rs1 += __shfl_xor_sync(0xffffffffu, rs1, 2);
        lr0 = lr0 * al0 + rs0;
        lr1 = lr1 * al1 + rs1;

        #pragma unroll
        for (int nt = 0; nt < 16; nt++) {
            oacc[nt][0] *= al0; oacc[nt][1] *= al0;
            oacc[nt][2] *= al1; oacc[nt][3] *= al1;
        }

        #pragma unroll
        for (int t = 0; t < 4; t++) {
            unsigned pa[4];
            pa[0] = ph01[2 * t];
            pa[1] = ph23[2 * t];
            pa[2] = ph01[2 * t + 1];
            pa[3] = ph23[2 * t + 1];
            #pragma unroll
            for (int nt = 0; nt < 16; nt++) {
                int vr = (8 * t + lk) * VPP + nt * 8 + l4;
                unsigned b_hi[2], b_lo[2];
                b_hi[0] = Vph[vr];
                b_hi[1] = Vph[vr + 4 * VPP];
                b_lo[0] = Vpl[vr];
                b_lo[1] = Vpl[vr + 4 * VPP];
                mma_f16_f32(oacc[nt], pa, b_hi);
                mma_f16_f32(oacc[nt], pa, b_lo);
            }
        }
        __syncthreads();
    }

    float il0 = 1.f / lr0, il1 = 1.f / lr1;
    int row0 = m0 + wm * 16 + l4;
    #pragma unroll
    for (int nt = 0; nt < 16; nt++) {
        int col = h * DHEAD + nt * 8 + 2 * lk;
        float a0 = oacc[nt][0] * il0, a1 = oacc[nt][1] * il0;
        float a2 = oacc[nt][2] * il1, a3 = oacc[nt][3] * il1;
        __half h0, l0, h1, l1;
        split_h_plain(a0, h0, l0); split_h_plain(a1, h1, l1);
        *(unsigned*)(oh + (rowbase + row0) * EMB + col) = pack_h2(h0, h1);
        *(unsigned*)(ol + (rowbase + row0) * EMB + col) = pack_h2(l0, l1);
        split_h_plain(a2, h0, l0); split_h_plain(a3, h1, l1);
        *(unsigned*)(oh + (rowbase + row0 + 8) * EMB + col) = pack_h2(h0, h1);
        *(unsigned*)(ol + (rowbase + row0 + 8) * EMB + col) = pack_h2(l0, l1);
    }
}

// ---------------------------------------------------------------------------
extern "C" void kernel_launch(void* const* d_in, const int* in_sizes, int n_in,
                              void* d_out, int out_size)
{
    const float* x    = (const float*)d_in[0];
    const float* mask = (const float*)d_in[1];
    const float* Wq = (const float*)d_in[2];  const float* bq = (const float*)d_in[3];
    const float* Aq = (const float*)d_in[4];  const float* Bq = (const float*)d_in[5];
    const float* Cq = (const float*)d_in[6];  const float* Rq = (const float*)d_in[7];
    const float* Wk = (const float*)d_in[8];  const float* bk = (const float*)d_in[9];
    const float* Ak = (const float*)d_in[10]; const float* Bk = (const float*)d_in[11];
    const float* Ck = (const float*)d_in[12]; const float* Rk = (const float*)d_in[13];
    const float* Wv = (const float*)d_in[14]; const float* bv = (const float*)d_in[15];
    const float* Av = (const float*)d_in[16]; const float* Bv = (const float*)d_in[17];
    const float* Cv = (const float*)d_in[18]; const float* Rv = (const float*)d_in[19];
    const float* Wo = (const float*)d_in[20]; const float* Ao = (const float*)d_in[21];
    const float* Bo = (const float*)d_in[22]; const float* Co = (const float*)d_in[23];
    const float* Ro = (const float*)d_in[24];

    float *q, *k, *v;
    __half *xh, *xl, *hh, *hl, *w16;
    unsigned *kph, *kpl, *vph, *vpl;
    cudaGetSymbolAddress((void**)&q,   g_q);
    cudaGetSymbolAddress((void**)&k,   g_k);
    cudaGetSymbolAddress((void**)&v,   g_v);
    cudaGetSymbolAddress((void**)&xh,  g_xh);
    cudaGetSymbolAddress((void**)&xl,  g_xl);
    cudaGetSymbolAddress((void**)&hh,  g_hh);
    cudaGetSymbolAddress((void**)&hl,  g_hl);
    cudaGetSymbolAddress((void**)&w16, g_w16);
    cudaGetSymbolAddress((void**)&kph, g_kph);
    cudaGetSymbolAddress((void**)&kpl, g_kpl);
    cudaGetSymbolAddress((void**)&vph, g_vph);
    cudaGetSymbolAddress((void**)&vpl, g_vpl);

    cudaFuncSetAttribute(flash_mma,
                         cudaFuncAttributeMaxDynamicSharedMemorySize, FA2_SMEM);
    cudaFuncSetAttribute(gemm_ps3,
                         cudaFuncAttributeMaxDynamicSharedMemorySize, GPS_SMEM);

    const size_t HSTR = (size_t)ROWS * 96;
    const size_t WSTR = (size_t)2048 * KAUG;

    // one-time packs
    pack_w16<<<dim3(2048, 4), 256>>>(Wq, Bq, Rq, Wk, Bk, Rk, Wv, Bv, Rv, Wo, Bo, Ro, w16);
    pack_x<<<(ROWS * EMB / 8) / 256, 256>>>(x, xh, xl);
    // aux terms for q/k/v (reads planes)
    aux_mma<<<dim3(3, ROWS / 128), 256>>>(xh, xl, mask, Aq, Cq, Ak, Ck, Av, Cv,
                                          hh, hl, hh + HSTR, hl + HSTR,
                                          hh + 2 * HSTR, hl + 2 * HSTR);
    // q/k/v projections in ONE launch (better wave packing)
    gemm_ps3<<<dim3(48, ROWS / 128), 256, GPS_SMEM>>>(
        xh, xl, hh, hl, HSTR, w16, WSTR, bq, bk, bv, q, k, v);
    // rope + flash packs
    rope_pack<<<(ROWS * NHEAD * 32 + 255) / 256, 256>>>(q, k, kph, kpl);
    vpack<<<(32 * 1024 * 128 + 255) / 256, 256>>>(v, vph, vpl);
    // flash attention -> writes att planes into xh/xl
    flash_mma<<<dim3(SEQ / 128, BATCH * NHEAD), 256, FA2_SMEM>>>(
        q, kph, kpl, vph, vpl, xh, xl);
    // output projection
    aux_mma<<<dim3(1, ROWS / 128), 256>>>(xh, xl, mask, Ao, Co, Ao, Co, Ao, Co,
                                          hh + 3 * HSTR, hl + 3 * HSTR,
                                          hh + 3 * HSTR, hl + 3 * HSTR,
                                          hh + 3 * HSTR, hl + 3 * HSTR);
    gemm_ps3<<<dim3(16, ROWS / 128), 256, GPS_SMEM>>>(
        xh, xl, hh + 3 * HSTR, hl + 3 * HSTR, HSTR, w16 + 3 * WSTR, WSTR,
        nullptr, nullptr, nullptr, (float*)d_out, (float*)d_out, (float*)d_out);
}

// round 16
// speedup vs baseline: 1.4167x; 1.0381x over previous
#include <cuda_runtime.h>
#include <cuda_bf16.h>
#include <cuda_fp16.h>
#include <cstdint>
#include <math.h>

#define BATCH 2
#define SEQ   2048
#define EMB   2048
#define NHEAD 16
#define DHEAD 128
#define NEXP_ 64
#define RLORA 32
#define ROWS  4096
#define KAUG  2144
#define NCH2  67          // K chunks of 32

// ---------------- scratch ----------------
__device__ float g_q[(size_t)ROWS * EMB];
__device__ float g_k[(size_t)ROWS * EMB];
__device__ float g_v[(size_t)ROWS * EMB];
__device__ __half g_xh[(size_t)ROWS * EMB];
__device__ __half g_xl[(size_t)ROWS * EMB];
__device__ __half g_hh[4][(size_t)ROWS * 96];
__device__ __half g_hl[4][(size_t)ROWS * 96];
__device__ __half g_w16[(size_t)4 * 2048 * KAUG];
__device__ unsigned g_kph[(size_t)32 * 2048 * 64];
__device__ unsigned g_kpl[(size_t)32 * 2048 * 64];
__device__ unsigned g_vph[(size_t)32 * 1024 * 128];
__device__ unsigned g_vpl[(size_t)32 * 1024 * 128];

// ---------------- helpers ----------------
__device__ __forceinline__ unsigned pack_bf2(__nv_bfloat16 a, __nv_bfloat16 b) {
    return (unsigned)__bfloat16_as_ushort(a) | ((unsigned)__bfloat16_as_ushort(b) << 16);
}
__device__ __forceinline__ void split_bf(float x, __nv_bfloat16& hi, __nv_bfloat16& lo) {
    hi = __float2bfloat16_rn(x);
    lo = __float2bfloat16_rn(x - __bfloat162float(hi));
}
__device__ __forceinline__ unsigned pack_h2(__half a, __half b) {
    __half2 t = __halves2half2(a, b);
    return *(unsigned*)&t;
}
__device__ __forceinline__ void split_h_plain(float x, __half& hi, __half& lo) {
    hi = __float2half_rn(x);
    lo = __float2half_rn(x - __half2float(hi));
}
__device__ __forceinline__ void mma_bf16(float* c, const unsigned* a, const unsigned* b) {
    asm volatile(
        "mma.sync.aligned.m16n8k16.row.col.f32.bf16.bf16.f32 "
        "{%0,%1,%2,%3}, {%4,%5,%6,%7}, {%8,%9}, {%0,%1,%2,%3};"
        : "+f"(c[0]), "+f"(c[1]), "+f"(c[2]), "+f"(c[3])
        : "r"(a[0]), "r"(a[1]), "r"(a[2]), "r"(a[3]), "r"(b[0]), "r"(b[1]));
}
__device__ __forceinline__ void mma_f16_f32(float* c, const unsigned* a, const unsigned* b) {
    asm volatile(
        "mma.sync.aligned.m16n8k16.row.col.f32.f16.f16.f32 "
        "{%0,%1,%2,%3}, {%4,%5,%6,%7}, {%8,%9}, {%0,%1,%2,%3};"
        : "+f"(c[0]), "+f"(c[1]), "+f"(c[2]), "+f"(c[3])
        : "r"(a[0]), "r"(a[1]), "r"(a[2]), "r"(a[3]), "r"(b[0]), "r"(b[1]));
}
__device__ __forceinline__ void ldsm_x4(unsigned* r, unsigned saddr) {
    asm volatile("ldmatrix.sync.aligned.m8n8.x4.shared.b16 {%0,%1,%2,%3}, [%4];"
        : "=r"(r[0]), "=r"(r[1]), "=r"(r[2]), "=r"(r[3]) : "r"(saddr));
}
__device__ __forceinline__ void ldsm_x2(unsigned* r, unsigned saddr) {
    asm volatile("ldmatrix.sync.aligned.m8n8.x2.shared.b16 {%0,%1}, [%2];"
        : "=r"(r[0]), "=r"(r[1]) : "r"(saddr));
}
__device__ __forceinline__ void cp16(unsigned saddr, const void* g) {
    asm volatile("cp.async.cg.shared.global [%0], [%1], 16;" :: "r"(saddr), "l"(g) : "memory");
}
#define CP_COMMIT asm volatile("cp.async.commit_group;\n" ::: "memory")
__device__ __forceinline__ unsigned s2u(const void* p) {
    unsigned a;
    asm("{ .reg .u64 t; cvta.to.shared.u64 t, %1; cvt.u32.u64 %0, t; }" : "=r"(a) : "l"(p));
    return a;
}

#define L2E 1.4426950408889634f
__device__ __forceinline__ float exp2q(float t) {
    t = fmaxf(t, -126.f);
    float z = t + 12582912.f;
    int ni = __float_as_int(z) - 0x4B400000;
    float r = t - (z - 12582912.f);
    float p = 1.3333558146e-3f;
    p = fmaf(p, r, 9.6181291876e-3f);
    p = fmaf(p, r, 5.5504108665e-2f);
    p = fmaf(p, r, 2.4022650696e-1f);
    p = fmaf(p, r, 6.9314718056e-1f);
    p = fmaf(p, r, 1.0f);
    return p * __int_as_float((ni + 127) << 23);
}

// ---------------------------------------------------------------------------
// pack_x: fp32 -> fp16 hi/lo planes
// ---------------------------------------------------------------------------
__global__ void pack_x(const float* __restrict__ src,
                       __half* __restrict__ dh, __half* __restrict__ dl)
{
    size_t i = ((size_t)blockIdx.x * 256 + threadIdx.x) * 8;
    float4 v0 = *(const float4*)(src + i);
    float4 v1 = *(const float4*)(src + i + 4);
    __half h[8], l[8];
    split_h_plain(v0.x, h[0], l[0]); split_h_plain(v0.y, h[1], l[1]);
    split_h_plain(v0.z, h[2], l[2]); split_h_plain(v0.w, h[3], l[3]);
    split_h_plain(v1.x, h[4], l[4]); split_h_plain(v1.y, h[5], l[5]);
    split_h_plain(v1.z, h[6], l[6]); split_h_plain(v1.w, h[7], l[7]);
    uint4 ph = make_uint4(pack_h2(h[0], h[1]), pack_h2(h[2], h[3]),
                          pack_h2(h[4], h[5]), pack_h2(h[6], h[7]));
    uint4 pl = make_uint4(pack_h2(l[0], l[1]), pack_h2(l[2], l[3]),
                          pack_h2(l[4], l[5]), pack_h2(l[6], l[7]));
    *(uint4*)(dh + i) = ph;
    *(uint4*)(dl + i) = pl;
}

// ---------------------------------------------------------------------------
// pack_w16: concat [W | Bl | Rr] rows -> fp16, KAUG stride, 4 projections
// ---------------------------------------------------------------------------
__global__ void pack_w16(
    const float* __restrict__ W0, const float* __restrict__ B0, const float* __restrict__ R0,
    const float* __restrict__ W1, const float* __restrict__ B1, const float* __restrict__ R1,
    const float* __restrict__ W2, const float* __restrict__ B2, const float* __restrict__ R2,
    const float* __restrict__ W3, const float* __restrict__ B3, const float* __restrict__ R3,
    __half* __restrict__ w16)
{
    const int n = blockIdx.x, p = blockIdx.y;
    const float* W = (p == 0) ? W0 : (p == 1) ? W1 : (p == 2) ? W2 : W3;
    const float* Bm = (p == 0) ? B0 : (p == 1) ? B1 : (p == 2) ? B2 : B3;
    const float* Rm = (p == 0) ? R0 : (p == 1) ? R1 : (p == 2) ? R2 : R3;
    __half* d = w16 + ((size_t)p * 2048 + n) * KAUG;

    for (int k = threadIdx.x * 4; k < KAUG; k += 1024) {
        float4 v;
        if (k < EMB)              v = *(const float4*)(W + (size_t)n * EMB + k);
        else if (k < EMB + RLORA) v = *(const float4*)(Bm + (size_t)n * RLORA + (k - EMB));
        else                      v = *(const float4*)(Rm + (size_t)n * NEXP_ + (k - EMB - RLORA));
        uint2 o = make_uint2(pack_h2(__float2half_rn(v.x), __float2half_rn(v.y)),
                             pack_h2(__float2half_rn(v.z), __float2half_rn(v.w)));
        *(uint2*)(d + k) = o;
    }
}

// ---------------------------------------------------------------------------
// aux GEMM (unchanged from R15)
// ---------------------------------------------------------------------------
__global__ __launch_bounds__(256) void aux_mma(
    const __half* __restrict__ xh, const __half* __restrict__ xl,
    const float* __restrict__ mask,
    const float* __restrict__ A0, const float* __restrict__ C0,
    const float* __restrict__ A1, const float* __restrict__ C1,
    const float* __restrict__ A2, const float* __restrict__ C2,
    __half* __restrict__ hh0, __half* __restrict__ hl0,
    __half* __restrict__ hh1, __half* __restrict__ hl1,
    __half* __restrict__ hh2, __half* __restrict__ hl2)
{
    __shared__ unsigned Ah[128][20], Al[128][20];
    __shared__ unsigned Bh[96][20];

    const int proj = blockIdx.x;
    const int m0 = blockIdx.y * 128;
    const float* A = (proj == 0) ? A0 : ((proj == 1) ? A1 : A2);
    const float* C = (proj == 0) ? C0 : ((proj == 1) ? C1 : C2);
    __half* hh = (proj == 0) ? hh0 : ((proj == 1) ? hh1 : hh2);
    __half* hl = (proj == 0) ? hl0 : ((proj == 1) ? hl1 : hl2);

    const int tid = threadIdx.x;
    const int lane = tid & 31, wid = tid >> 5;
    const int l4 = lane >> 2, lk = lane & 3;
    const int warp_m = wid & 3, warp_n = wid >> 2;

    float c[2][6][4];
    #pragma unroll
    for (int mt = 0; mt < 2; mt++)
        #pragma unroll
        for (int nt = 0; nt < 6; nt++)
            #pragma unroll
            for (int i = 0; i < 4; i++) c[mt][nt][i] = 0.f;

    for (int k0 = 0; k0 < EMB; k0 += 32) {
        #pragma unroll
        for (int i = 0; i < 4; i++) {
            int lin = tid + 256 * i;
            int r = lin >> 3, half8 = lin & 7;
            int pl = half8 >> 2, qq = half8 & 3;
            const __half* src = (pl == 0) ? xh : xl;
            uint4 vv = *(const uint4*)(src + (size_t)(m0 + r) * EMB + k0 + qq * 8);
            unsigned* dst = (pl == 0) ? &Ah[r][qq * 4] : &Al[r][qq * 4];
            *(uint4*)dst = vv;
        }
        #pragma unroll
        for (int i = 0; i < 3; i++) {
            int lin = tid + 256 * i;
            if (lin < 768) {
                int r = lin >> 3, c4 = (lin & 7) << 2;
                const float* src = (r < 32) ? (A + (size_t)r * EMB)
                                            : (C + (size_t)(r - 32) * EMB);
                float4 vb = *(const float4*)(src + k0 + c4);
                *(uint2*)&Bh[r][c4 >> 1] = make_uint2(
                    pack_h2(__float2half_rn(vb.x), __float2half_rn(vb.y)),
                    pack_h2(__float2half_rn(vb.z), __float2half_rn(vb.w)));
            }
        }
        __syncthreads();

        #pragma unroll
        for (int ks = 0; ks < 2; ks++) {
            const int kw = ks * 8;
            unsigned ah[2][4], al[2][4];
            #pragma unroll
            for (int mt = 0; mt < 2; mt++) {
                int rb = warp_m * 32 + mt * 16 + l4;
                ah[mt][0] = Ah[rb][kw + lk];
                ah[mt][1] = Ah[rb + 8][kw + lk];
                ah[mt][2] = Ah[rb][kw + 4 + lk];
                ah[mt][3] = Ah[rb + 8][kw + 4 + lk];
                al[mt][0] = Al[rb][kw + lk];
                al[mt][1] = Al[rb + 8][kw + lk];
                al[mt][2] = Al[rb][kw + 4 + lk];
                al[mt][3] = Al[rb + 8][kw + 4 + lk];
            }
            #pragma unroll
            for (int nt = 0; nt < 6; nt++) {
                int cb = warp_n * 48 + nt * 8 + l4;
                unsigned bh[2];
                bh[0] = Bh[cb][kw + lk];
                bh[1] = Bh[cb][kw + 4 + lk];
                #pragma unroll
                for (int mt = 0; mt < 2; mt++) {
                    mma_f16_f32(c[mt][nt], ah[mt], bh);
                    mma_f16_f32(c[mt][nt], al[mt], bh);
                }
            }
        }
        __syncthreads();
    }

    #pragma unroll
    for (int mt = 0; mt < 2; mt++) {
        int r0 = m0 + warp_m * 32 + mt * 16 + l4;
        #pragma unroll
        for (int nt = 0; nt < 6; nt++) {
            int u = warp_n * 48 + nt * 8 + 2 * lk;
            #pragma unroll
            for (int half = 0; half < 2; half++) {
                int row = r0 + half * 8;
                float v0 = c[mt][nt][half * 2 + 0];
                float v1 = c[mt][nt][half * 2 + 1];
                float s0 = v0 / (1.f + __expf(-v0));
                float s1 = v1 / (1.f + __expf(-v1));
                if (u >= 32)     s0 *= mask[(size_t)row * NEXP_ + (u - 32)];
                if (u + 1 >= 32) s1 *= mask[(size_t)row * NEXP_ + (u + 1 - 32)];
                __half h0, l0, h1, l1;
                split_h_plain(s0, h0, l0);
                split_h_plain(s1, h1, l1);
                hh[(size_t)row * 96 + u]     = h0;
                hh[(size_t)row * 96 + u + 1] = h1;
                hl[(size_t)row * 96 + u]     = l0;
                hl[(size_t)row * 96 + u + 1] = l1;
            }
        }
    }
}

// ---------------------------------------------------------------------------
// Presplit fp16 2-term GEMM, 3-stage cp.async pipeline + ldmatrix fragments.
// ---------------------------------------------------------------------------
#define PLW   (128 * 20)
#define STGW  (3 * PLW)
#define GPS_SMEM (3 * STGW * 4)

__global__ __launch_bounds__(256, 2) void gemm_ps3(
    const __half* __restrict__ xh, const __half* __restrict__ xl,
    const __half* __restrict__ hhb, const __half* __restrict__ hlb, size_t hstr,
    const __half* __restrict__ w16b, size_t wstr,
    const float* __restrict__ b0, const float* __restrict__ b1,
    const float* __restrict__ b2,
    float* __restrict__ o0, float* __restrict__ o1, float* __restrict__ o2)
{
    extern __shared__ unsigned smw[];
    const unsigned dsm = s2u(smw);
    const int tid = threadIdx.x;
    const int lane = tid & 31, wid = tid >> 5;
    const int l4 = lane >> 2, lk = lane & 3;
    const int warp_m = wid & 3, warp_n = wid >> 2;
    const int p = blockIdx.x >> 4;
    const int m0 = blockIdx.y * 128, n0 = (blockIdx.x & 15) * 128;
    const __half* hh  = hhb + (size_t)p * hstr;
    const __half* hl  = hlb + (size_t)p * hstr;
    const __half* w16 = w16b + (size_t)p * wstr;
    const float* bias = (p == 0) ? b0 : (p == 1) ? b1 : b2;
    float* out        = (p == 0) ? o0 : (p == 1) ? o1 : o2;

    float c[2][8][4];
    #pragma unroll
    for (int mt = 0; mt < 2; mt++)
        #pragma unroll
        for (int nt = 0; nt < 8; nt++)
            #pragma unroll
            for (int i = 0; i < 4; i++) c[mt][nt][i] = 0.f;

    const int r0f = tid >> 2, q0f = tid & 3;
    // ldmatrix lane-based address offsets (in words)
    const int aOfs = (warp_m * 32 + (lane & 15)) * 20 + (lane >> 4) * 4;
    const int bOfs = (warp_n * 64 + (lane & 7)) * 20 + ((lane >> 3) & 1) * 4;

#define FILLP(STG, CC) do {                                                     \
    int c_ = (CC);                                                              \
    unsigned sb_ = dsm + (STG) * STGW * 4;                                      \
    const __half *pah_, *pal_; int str_;                                        \
    if (c_ < 64) { pah_ = xh + (size_t)m0 * EMB + c_ * 32;                      \
                   pal_ = xl + (size_t)m0 * EMB + c_ * 32; str_ = EMB; }        \
    else         { pah_ = hh + (size_t)m0 * 96 + (c_ - 64) * 32;                \
                   pal_ = hl + (size_t)m0 * 96 + (c_ - 64) * 32; str_ = 96; }   \
    const __half* pw_ = w16 + (size_t)n0 * KAUG + c_ * 32;                      \
    cp16(sb_ + (r0f * 20 + q0f * 4) * 4,        pah_ + (size_t)r0f * str_ + q0f * 8); \
    cp16(sb_ + ((r0f + 64) * 20 + q0f * 4) * 4, pah_ + (size_t)(r0f + 64) * str_ + q0f * 8); \
    cp16(sb_ + (PLW + r0f * 20 + q0f * 4) * 4,        pal_ + (size_t)r0f * str_ + q0f * 8); \
    cp16(sb_ + (PLW + (r0f + 64) * 20 + q0f * 4) * 4, pal_ + (size_t)(r0f + 64) * str_ + q0f * 8); \
    cp16(sb_ + (2 * PLW + r0f * 20 + q0f * 4) * 4,        pw_ + (size_t)r0f * KAUG + q0f * 8); \
    cp16(sb_ + (2 * PLW + (r0f + 64) * 20 + q0f * 4) * 4, pw_ + (size_t)(r0f + 64) * KAUG + q0f * 8); \
} while (0)

    FILLP(0, 0); CP_COMMIT;
    FILLP(1, 1); CP_COMMIT;

    for (int cc = 0; cc < NCH2; cc++) {
        asm volatile("cp.async.wait_group 1;" ::: "memory");
        __syncthreads();

        int nf = cc + 2;
        if (nf < NCH2) FILLP(nf % 3, nf);
        CP_COMMIT;

        const unsigned sb = dsm + (cc % 3) * STGW * 4;
        const unsigned aAddr = sb + aOfs * 4;
        const unsigned bAddr = sb + (2 * PLW + bOfs) * 4;

        #pragma unroll
        for (int ks = 0; ks < 2; ks++) {
            unsigned a_hi[2][4], a_lo[2][4];
            #pragma unroll
            for (int mt = 0; mt < 2; mt++) {
                ldsm_x4(a_hi[mt], aAddr + (mt * 320 + ks * 8) * 4);
                ldsm_x4(a_lo[mt], aAddr + (PLW + mt * 320 + ks * 8) * 4);
            }
            #pragma unroll
            for (int nt = 0; nt < 8; nt++) {
                unsigned bh[2];
                ldsm_x2(bh, bAddr + (nt * 160 + ks * 8) * 4);
                #pragma unroll
                for (int mt = 0; mt < 2; mt++) {
                    mma_f16_f32(c[mt][nt], a_hi[mt], bh);
                    mma_f16_f32(c[mt][nt], a_lo[mt], bh);
                }
            }
        }
    }
#undef FILLP

    float2 bv[8];
    #pragma unroll
    for (int nt = 0; nt < 8; nt++) {
        int col = n0 + warp_n * 64 + nt * 8 + 2 * lk;
        if (bias) bv[nt] = *(const float2*)(bias + col);
        else      bv[nt] = make_float2(0.f, 0.f);
    }
    #pragma unroll
    for (int mt = 0; mt < 2; mt++) {
        int r0 = m0 + warp_m * 32 + mt * 16 + l4;
        #pragma unroll
        for (int nt = 0; nt < 8; nt++) {
            int col = n0 + warp_n * 64 + nt * 8 + 2 * lk;
            float2 q0 = make_float2(c[mt][nt][0] + bv[nt].x, c[mt][nt][1] + bv[nt].y);
            float2 q1 = make_float2(c[mt][nt][2] + bv[nt].x, c[mt][nt][3] + bv[nt].y);
            *(float2*)(out + (size_t)r0 * EMB + col)       = q0;
            *(float2*)(out + (size_t)(r0 + 8) * EMB + col) = q1;
        }
    }
}

// ---------------------------------------------------------------------------
// rope_pack / vpack (unchanged)
// ---------------------------------------------------------------------------
__global__ void rope_pack(float* __restrict__ q, const float* __restrict__ k,
                          unsigned* __restrict__ kph, unsigned* __restrict__ kpl)
{
    int idx = blockIdx.x * blockDim.x + threadIdx.x;
    if (idx >= ROWS * NHEAD * 32) return;
    int jj  = idx & 31;
    int h   = (idx >> 5) & 15;
    int row = idx >> 9;
    int s   = row & (SEQ - 1);
    int b   = row >> 11;

    float sn[2], cs[2];
    #pragma unroll
    for (int t = 0; t < 2; t++) {
        int d = 2 * jj + t;
        float e = (float)(2 * d) * (1.0f / 128.0f);
        float inv = powf(10000.0f, -e);
        sincosf((float)s * inv, &sn[t], &cs[t]);
    }

    size_t base = (size_t)row * EMB + h * DHEAD;
    float qlo[2], qhi2[2], klo[2], khi2[2];
    #pragma unroll
    for (int t = 0; t < 2; t++) {
        int d = 2 * jj + t;
        float x1 = q[base + d], x2 = q[base + d + 64];
        qlo[t]  = x1 * cs[t] - x2 * sn[t];
        qhi2[t] = x2 * cs[t] + x1 * sn[t];
        float y1 = k[base + d], y2 = k[base + d + 64];
        klo[t]  = y1 * cs[t] - y2 * sn[t];
        khi2[t] = y2 * cs[t] + y1 * sn[t];
    }
    #pragma unroll
    for (int t = 0; t < 2; t++) {
        q[base + 2 * jj + t]      = qlo[t];
        q[base + 2 * jj + t + 64] = qhi2[t];
    }
    int bh = b * NHEAD + h;
    size_t kbase = ((size_t)bh * SEQ + s) * 64;
    __nv_bfloat16 h0, l0, h1, l1;
    split_bf(klo[0], h0, l0); split_bf(klo[1], h1, l1);
    kph[kbase + jj] = pack_bf2(h0, h1);
    kpl[kbase + jj] = pack_bf2(l0, l1);
    split_bf(khi2[0], h0, l0); split_bf(khi2[1], h1, l1);
    kph[kbase + jj + 32] = pack_bf2(h0, h1);
    kpl[kbase + jj + 32] = pack_bf2(l0, l1);
}

__global__ void vpack(const float* __restrict__ v,
                      unsigned* __restrict__ vph, unsigned* __restrict__ vpl)
{
    int idx = blockIdx.x * blockDim.x + threadIdx.x;
    if (idx >= 32 * 1024 * 128) return;
    int nn = idx & 127;
    int kw = (idx >> 7) & 1023;
    int bh = idx >> 17;
    int b = bh >> 4, h = bh & 15;
    size_t addr = ((size_t)(b * SEQ + 2 * kw)) * EMB + h * DHEAD + nn;
    float v0 = v[addr], v1 = v[addr + EMB];
    __half h0, l0, h1, l1;
    split_h_plain(v0, h0, l0); split_h_plain(v1, h1, l1);
    vph[idx] = pack_h2(h0, h1);
    vpl[idx] = pack_h2(l0, l1);
}

// ---------------------------------------------------------------------------
// Flash attention (unchanged from R15)
// ---------------------------------------------------------------------------
#define KPP 68
#define VPP 136
#define FA2_SMEM ((64 * KPP * 2 + 32 * VPP * 2) * 4)

__global__ __launch_bounds__(256) void flash_mma(
    const float* __restrict__ q,
    const unsigned* __restrict__ kph, const unsigned* __restrict__ kpl,
    const unsigned* __restrict__ vph, const unsigned* __restrict__ vpl,
    __half* __restrict__ oh, __half* __restrict__ ol)
{
    extern __shared__ unsigned sw_[];
    unsigned* Kph = sw_;
    unsigned* Kpl = Kph + 64 * KPP;
    unsigned* Vph = Kpl + 64 * KPP;
    unsigned* Vpl = Vph + 32 * VPP;

    const int tid = threadIdx.x;
    const int lane = tid & 31, wm = tid >> 5;
    const int l4 = lane >> 2, lk = lane & 3;
    const int iblk = (int)gridDim.x - 1 - (int)blockIdx.x;
    const int bh = blockIdx.y;
    const int b = bh >> 4, h = bh & 15;
    const size_t rowbase = (size_t)b * SEQ;
    const int m0 = iblk * 128;
    const float scale = 0.08838834764831845f;

    unsigned qh[8][4], ql[8][4];
    {
        const int r0 = m0 + wm * 16 + l4;
        #pragma unroll
        for (int s = 0; s < 8; s++) {
            #pragma unroll
            for (int f = 0; f < 4; f++) {
                int r = r0 + ((f & 1) ? 8 : 0);
                int d = 16 * s + 2 * lk + ((f & 2) ? 8 : 0);
                float2 qv = *(const float2*)(q + (rowbase + r) * EMB + h * DHEAD + d);
                float x = qv.x * scale, y = qv.y * scale;
                __nv_bfloat16 hx, lx, hy, ly;
                split_bf(x, hx, lx); split_bf(y, hy, ly);
                qh[s][f] = pack_bf2(hx, hy);
                ql[s][f] = pack_bf2(lx, ly);
            }
        }
    }

    float mr0 = -1e30f, mr1 = -1e30f, lr0 = 0.f, lr1 = 0.f;
    float oacc[16][4];
    #pragma unroll
    for (int nt = 0; nt < 16; nt++)
        #pragma unroll
        for (int i = 0; i < 4; i++) oacc[nt][i] = 0.f;

    const size_t kbase = (size_t)bh * SEQ * 64;
    const size_t vbase = (size_t)bh * 1024 * 128;

    const int ntiles = 2 * iblk + 2;
    for (int j = 0; j < ntiles; j++) {
        #pragma unroll
        for (int i = 0; i < 4; i++) {
            int lin = tid + 256 * i;
            int r = lin >> 4, c4 = (lin & 15) << 2;
            size_t src = kbase + (size_t)(j * 64 + r) * 64 + c4;
            *(uint4*)&Kph[r * KPP + c4] = *(const uint4*)(kph + src);
            *(uint4*)&Kpl[r * KPP + c4] = *(const uint4*)(kpl + src);
        }
        #pragma unroll
        for (int i = 0; i < 4; i++) {
            int lin = tid + 256 * i;
            int r = lin >> 5, c4 = (lin & 31) << 2;
            size_t src = vbase + (size_t)(j * 32 + r) * 128 + c4;
            *(uint4*)&Vph[r * VPP + c4] = *(const uint4*)(vph + src);
            *(uint4*)&Vpl[r * VPP + c4] = *(const uint4*)(vpl + src);
        }
        __syncthreads();

        float sacc[8][4];
        #pragma unroll
        for (int nt = 0; nt < 8; nt++)
            #pragma unroll
            for (int i = 0; i < 4; i++) sacc[nt][i] = 0.f;

        #pragma unroll
        for (int s = 0; s < 8; s++) {
            #pragma unroll
            for (int nt = 0; nt < 8; nt++) {
                int kr = (nt * 8 + l4) * KPP + 8 * s + lk;
                unsigned b_hi[2], b_lo[2];
                b_hi[0] = Kph[kr];
                b_hi[1] = Kph[kr + 4];
                b_lo[0] = Kpl[kr];
                b_lo[1] = Kpl[kr + 4];
                mma_bf16(sacc[nt], qh[s], b_hi);
                mma_bf16(sacc[nt], qh[s], b_lo);
                mma_bf16(sacc[nt], ql[s], b_hi);
            }
        }

        if (j >= 2 * iblk) {
            int row0 = m0 + wm * 16 + l4;
            #pragma unroll
            for (int nt = 0; nt < 8; nt++) {
                int col = j * 64 + nt * 8 + 2 * lk;
                if (col     > row0)     sacc[nt][0] = -1e30f;
                if (col + 1 > row0)     sacc[nt][1] = -1e30f;
                if (col     > row0 + 8) sacc[nt][2] = -1e30f;
                if (col + 1 > row0 + 8) sacc[nt][3] = -1e30f;
            }
        }

        float mx0 = -1e30f, mx1 = -1e30f;
        #pragma unroll
        for (int nt = 0; nt < 8; nt++) {
            mx0 = fmaxf(mx0, fmaxf(sacc[nt][0], sacc[nt][1]));
            mx1 = fmaxf(mx1, fmaxf(sacc[nt][2], sacc[nt][3]));
        }
        mx0 = fmaxf(mx0, __shfl_xor_sync(0xffffffffu, mx0, 1));
        mx0 = fmaxf(mx0, __shfl_xor_sync(0xffffffffu, mx0, 2));
        mx1 = fmaxf(mx1, __shfl_xor_sync(0xffffffffu, mx1, 1));
        mx1 = fmaxf(mx1, __shfl_xor_sync(0xffffffffu, mx1, 2));

        float mn0 = fmaxf(mr0, mx0), mn1 = fmaxf(mr1, mx1);
        float al0 = exp2q((mr0 - mn0) * L2E);
        float al1 = exp2q((mr1 - mn1) * L2E);
        mr0 = mn0; mr1 = mn1;
        float mnl0 = mn0 * L2E, mnl1 = mn1 * L2E;

        unsigned ph01[8], ph23[8];
        float rs0 = 0.f, rs1 = 0.f;
        #pragma unroll
        for (int nt = 0; nt < 8; nt++) {
            float p0 = exp2q(fmaf(sacc[nt][0], L2E, -mnl0));
            float p1 = exp2q(fmaf(sacc[nt][1], L2E, -mnl0));
            float p2 = exp2q(fmaf(sacc[nt][2], L2E, -mnl1));
            float p3 = exp2q(fmaf(sacc[nt][3], L2E, -mnl1));
            rs0 += p0 + p1; rs1 += p2 + p3;
            ph01[nt] = pack_h2(__float2half_rn(p0), __float2half_rn(p1));
            ph23[nt] = pack_h2(__float2half_rn(p2), __float2half_rn(p3));
        }
        rs0 += __shfl_xor_sync(0xffffffffu, rs0, 1);
        rs0 += __shfl_xor_sync(0xffffffffu, rs0, 2);
        rs1 += __shfl_xor_sync(0xffffffffu, rs1, 1);
        rs1 += __shfl_xor_sync(0xffffffffu, rs1, 2);
        lr0 = lr0 * al0 + rs0;
        lr1 = lr1 * al1 + rs1;

        #pragma unroll
        for (int nt = 0; nt < 16; nt++) {
            oacc[nt][0] *= al0; oacc[nt][1] *= al0;
            oacc[nt][2] *= al1; oacc[nt][3] *= al1;
        }

        #pragma unroll
        for (int t = 0; t < 4; t++) {
            unsigned pa[4];
            pa[0] = ph01[2 * t];
            pa[1] = ph23[2 * t];
            pa[2] = ph01[2 * t + 1];
            pa[3] = ph23[2 * t + 1];
            #pragma unroll
            for (int nt = 0; nt < 16; nt++) {
                int vr = (8 * t + lk) * VPP + nt * 8 + l4;
                unsigned b_hi[2], b_lo[2];
                b_hi[0] = Vph[vr];
                b_hi[1] = Vph[vr + 4 * VPP];
                b_lo[0] = Vpl[vr];
                b_lo[1] = Vpl[vr + 4 * VPP];
                mma_f16_f32(oacc[nt], pa, b_hi);
                mma_f16_f32(oacc[nt], pa, b_lo);
            }
        }
        __syncthreads();
    }

    float il0 = 1.f / lr0, il1 = 1.f / lr1;
    int row0 = m0 + wm * 16 + l4;
    #pragma unroll
    for (int nt = 0; nt < 16; nt++) {
        int col = h * DHEAD + nt * 8 + 2 * lk;
        float a0 = oacc[nt][0] * il0, a1 = oacc[nt][1] * il0;
        float a2 = oacc[nt][2] * il1, a3 = oacc[nt][3] * il1;
        __half h0, l0, h1, l1;
        split_h_plain(a0, h0, l0); split_h_plain(a1, h1, l1);
        *(unsigned*)(oh + (rowbase + row0) * EMB + col) = pack_h2(h0, h1);
        *(unsigned*)(ol + (rowbase + row0) * EMB + col) = pack_h2(l0, l1);
        split_h_plain(a2, h0, l0); split_h_plain(a3, h1, l1);
        *(unsigned*)(oh + (rowbase + row0 + 8) * EMB + col) = pack_h2(h0, h1);
        *(unsigned*)(ol + (rowbase + row0 + 8) * EMB + col) = pack_h2(l0, l1);
    }
}

// ---------------------------------------------------------------------------
extern "C" void kernel_launch(void* const* d_in, const int* in_sizes, int n_in,
                              void* d_out, int out_size)
{
    const float* x    = (const float*)d_in[0];
    const float* mask = (const float*)d_in[1];
    const float* Wq = (const float*)d_in[2];  const float* bq = (const float*)d_in[3];
    const float* Aq = (const float*)d_in[4];  const float* Bq = (const float*)d_in[5];
    const float* Cq = (const float*)d_in[6];  const float* Rq = (const float*)d_in[7];
    const float* Wk = (const float*)d_in[8];  const float* bk = (const float*)d_in[9];
    const float* Ak = (const float*)d_in[10]; const float* Bk = (const float*)d_in[11];
    const float* Ck = (const float*)d_in[12]; const float* Rk = (const float*)d_in[13];
    const float* Wv = (const float*)d_in[14]; const float* bv = (const float*)d_in[15];
    const float* Av = (const float*)d_in[16]; const float* Bv = (const float*)d_in[17];
    const float* Cv = (const float*)d_in[18]; const float* Rv = (const float*)d_in[19];
    const float* Wo = (const float*)d_in[20]; const float* Ao = (const float*)d_in[21];
    const float* Bo = (const float*)d_in[22]; const float* Co = (const float*)d_in[23];
    const float* Ro = (const float*)d_in[24];

    float *q, *k, *v;
    __half *xh, *xl, *hh, *hl, *w16;
    unsigned *kph, *kpl, *vph, *vpl;
    cudaGetSymbolAddress((void**)&q,   g_q);
    cudaGetSymbolAddress((void**)&k,   g_k);
    cudaGetSymbolAddress((void**)&v,   g_v);
    cudaGetSymbolAddress((void**)&xh,  g_xh);
    cudaGetSymbolAddress((void**)&xl,  g_xl);
    cudaGetSymbolAddress((void**)&hh,  g_hh);
    cudaGetSymbolAddress((void**)&hl,  g_hl);
    cudaGetSymbolAddress((void**)&w16, g_w16);
    cudaGetSymbolAddress((void**)&kph, g_kph);
    cudaGetSymbolAddress((void**)&kpl, g_kpl);
    cudaGetSymbolAddress((void**)&vph, g_vph);
    cudaGetSymbolAddress((void**)&vpl, g_vpl);

    cudaFuncSetAttribute(flash_mma,
                         cudaFuncAttributeMaxDynamicSharedMemorySize, FA2_SMEM);
    cudaFuncSetAttribute(gemm_ps3,
                         cudaFuncAttributeMaxDynamicSharedMemorySize, GPS_SMEM);

    const size_t HSTR = (size_t)ROWS * 96;
    const size_t WSTR = (size_t)2048 * KAUG;

    // one-time packs
    pack_w16<<<dim3(2048, 4), 256>>>(Wq, Bq, Rq, Wk, Bk, Rk, Wv, Bv, Rv, Wo, Bo, Ro, w16);
    pack_x<<<(ROWS * EMB / 8) / 256, 256>>>(x, xh, xl);
    // aux terms for q/k/v
    aux_mma<<<dim3(3, ROWS / 128), 256>>>(xh, xl, mask, Aq, Cq, Ak, Ck, Av, Cv,
                                          hh, hl, hh + HSTR, hl + HSTR,
                                          hh + 2 * HSTR, hl + 2 * HSTR);
    // q/k/v projections in ONE launch
    gemm_ps3<<<dim3(48, ROWS / 128), 256, GPS_SMEM>>>(
        xh, xl, hh, hl, HSTR, w16, WSTR, bq, bk, bv, q, k, v);
    // rope + flash packs
    rope_pack<<<(ROWS * NHEAD * 32 + 255) / 256, 256>>>(q, k, kph, kpl);
    vpack<<<(32 * 1024 * 128 + 255) / 256, 256>>>(v, vph, vpl);
    // flash attention -> writes att planes into xh/xl
    flash_mma<<<dim3(SEQ / 128, BATCH * NHEAD), 256, FA2_SMEM>>>(
        q, kph, kpl, vph, vpl, xh, xl);
    // output projection
    aux_mma<<<dim3(1, ROWS / 128), 256>>>(xh, xl, mask, Ao, Co, Ao, Co, Ao, Co,
                                          hh + 3 * HSTR, hl + 3 * HSTR,
                                          hh + 3 * HSTR, hl + 3 * HSTR,
                                          hh + 3 * HSTR, hl + 3 * HSTR);
    gemm_ps3<<<dim3(16, ROWS / 128), 256, GPS_SMEM>>>(
        xh, xl, hh + 3 * HSTR, hl + 3 * HSTR, HSTR, w16 + 3 * WSTR, WSTR,
        nullptr, nullptr, nullptr, (float*)d_out, (float*)d_out, (float*)d_out);
}